// round 1
// baseline (speedup 1.0000x reference)
#include <cuda_runtime.h>
#include <math.h>

// Problem constants
#define BB 4
#define TT 2049
#define CC 1024
#define HH 16
#define DD 64
#define MROWS (BB*TT)          // 8196
#define QKV_COLS (3*CC)        // 3072

// Scratch (device globals: allocation-free, graph-capturable)
__device__ float g_qkv[(size_t)MROWS * QKV_COLS];   // (B*T, 3C)
__device__ float g_y[(size_t)MROWS * CC];           // (B*T, C)

// ---------------------------------------------------------------------------
// SGEMM: C = A(MxK) * B(KxN), row-major, fp32.
// 128x128 block tile, K-tile 8, 256 threads, 8x8 per-thread microtile.
// Requires: N % 128 == 0, K % 8 == 0. M guarded.
// ---------------------------------------------------------------------------
__global__ __launch_bounds__(256) void sgemm_kernel(
    const float* __restrict__ A, const float* __restrict__ B,
    float* __restrict__ C, int M, int N, int K)
{
    __shared__ float As[8][128];   // [k][m]
    __shared__ float Bs[8][128];   // [k][n]

    const int tid = threadIdx.x;
    const int bm = blockIdx.y * 128;
    const int bn = blockIdx.x * 128;

    const int a_row = tid >> 1;          // 0..127
    const int a_col = (tid & 1) << 2;    // 0 or 4
    const int b_row = tid >> 5;          // 0..7
    const int b_col = (tid & 31) << 2;   // 0..124

    const int ty = tid >> 4;   // 0..15 -> row group
    const int tx = tid & 15;   // 0..15 -> col group

    float acc[8][8];
#pragma unroll
    for (int i = 0; i < 8; ++i)
#pragma unroll
        for (int j = 0; j < 8; ++j) acc[i][j] = 0.f;

    const bool aOK = (bm + a_row) < M;
    const float* Aptr = A + (size_t)(bm + a_row) * K + a_col;
    const float* Bptr = B + (size_t)b_row * N + bn + b_col;

    for (int k0 = 0; k0 < K; k0 += 8) {
        float4 av = aOK ? *(const float4*)(Aptr + k0)
                        : make_float4(0.f, 0.f, 0.f, 0.f);
        float4 bv = *(const float4*)(Bptr + (size_t)k0 * N);

        As[a_col + 0][a_row] = av.x;
        As[a_col + 1][a_row] = av.y;
        As[a_col + 2][a_row] = av.z;
        As[a_col + 3][a_row] = av.w;
        *(float4*)&Bs[b_row][b_col] = bv;
        __syncthreads();

#pragma unroll
        for (int k = 0; k < 8; ++k) {
            float a[8], b[8];
            *(float4*)&a[0] = *(const float4*)&As[k][ty * 8];
            *(float4*)&a[4] = *(const float4*)&As[k][ty * 8 + 4];
            *(float4*)&b[0] = *(const float4*)&Bs[k][tx * 8];
            *(float4*)&b[4] = *(const float4*)&Bs[k][tx * 8 + 4];
#pragma unroll
            for (int i = 0; i < 8; ++i)
#pragma unroll
                for (int j = 0; j < 8; ++j)
                    acc[i][j] = fmaf(a[i], b[j], acc[i][j]);
        }
        __syncthreads();
    }

#pragma unroll
    for (int i = 0; i < 8; ++i) {
        int row = bm + ty * 8 + i;
        if (row < M) {
            float* Crow = C + (size_t)row * N + bn + tx * 8;
            *(float4*)(Crow + 0) = make_float4(acc[i][0], acc[i][1], acc[i][2], acc[i][3]);
            *(float4*)(Crow + 4) = make_float4(acc[i][4], acc[i][5], acc[i][6], acc[i][7]);
        }
    }
}

// ---------------------------------------------------------------------------
// Flash attention (fp32, online softmax).
// Block = (query tile of 64 rows) x (one (b,h)). 256 threads = 8 warps.
// Warp w owns query rows w*8..w*8+7; lane owns 2 columns (key cols for S,
// head dims for O). Causal mask + full-attention row t==0.
// ---------------------------------------------------------------------------
__global__ __launch_bounds__(256) void attn_kernel(
    const float* __restrict__ qkv, float* __restrict__ y)
{
    extern __shared__ float sm[];
    const int P = 66;                    // row pitch (words), 8B-aligned pairs
    float* Qs = sm;                      // [64][P]  (qrow, d)
    float* Kt = sm + 64 * P;             // [64][P]  (d, keycol)  TRANSPOSED
    float* Vs = sm + 2 * 64 * P;         // [64][P]  (keyrow, d)
    float* Ss = sm + 3 * 64 * P;         // [64][P]  (qrow, keycol)

    const int tid  = threadIdx.x;
    const int warp = tid >> 5;
    const int lane = tid & 31;
    const int qt = blockIdx.x;
    const int bh = blockIdx.y;
    const int b = bh >> 4, h = bh & 15;
    const int t0 = qt * 64;

    const size_t rowStride = QKV_COLS;
    const float* qbase = qkv + (size_t)b * TT * rowStride + h * DD;
    const float* kbase = qbase + CC;
    const float* vbase = qbase + 2 * CC;

    // load Q tile (zero-fill padding rows)
    for (int idx = tid; idx < 64 * DD; idx += 256) {
        int r = idx >> 6, c = idx & 63;
        int t = t0 + r;
        Qs[r * P + c] = (t < TT) ? qbase[(size_t)t * rowStride + c] : 0.f;
    }

    const float scale = 0.125f;  // 1/sqrt(64)
    const int c0 = lane * 2;

    float m_i[8], l_i[8], o0[8], o1[8];
#pragma unroll
    for (int i = 0; i < 8; ++i) { m_i[i] = -INFINITY; l_i[i] = 0.f; o0[i] = 0.f; o1[i] = 0.f; }

    // qt==0 contains the state row (t=0) that attends to everything
    const int nk = (qt == 0) ? ((TT + 63) >> 6) : (qt + 1);

    for (int kt = 0; kt < nk; ++kt) {
        const int s0 = kt * 64;
        __syncthreads();   // previous-iteration smem reads done
        // load K (transposed) and V tiles
        for (int idx = tid; idx < 64 * DD; idx += 256) {
            int r = idx >> 6, c = idx & 63;   // r = key-local, c = d
            int s = s0 + r;
            float kk = (s < TT) ? kbase[(size_t)s * rowStride + c] : 0.f;
            float vv = (s < TT) ? vbase[(size_t)s * rowStride + c] : 0.f;
            Kt[c * P + r] = kk;
            Vs[r * P + c] = vv;
        }
        __syncthreads();

        // S = Q K^T (rows warp*8..+7, cols c0, c0+1)
        float sA[8], sB[8];
#pragma unroll
        for (int i = 0; i < 8; ++i) { sA[i] = 0.f; sB[i] = 0.f; }
#pragma unroll 16
        for (int d = 0; d < DD; ++d) {
            float2 kk = *(const float2*)&Kt[d * P + c0];
            const float* qrow = &Qs[(warp * 8) * P + d];
#pragma unroll
            for (int i = 0; i < 8; ++i) {
                float q = qrow[i * P];
                sA[i] = fmaf(q, kk.x, sA[i]);
                sB[i] = fmaf(q, kk.y, sB[i]);
            }
        }

        // online softmax + stage P to smem
#pragma unroll
        for (int i = 0; i < 8; ++i) {
            int t = t0 + warp * 8 + i;
            int sIdxA = s0 + c0, sIdxB = sIdxA + 1;
            bool okA = (sIdxA < TT) && (sIdxA <= t || t == 0);
            bool okB = (sIdxB < TT) && (sIdxB <= t || t == 0);
            float a = okA ? sA[i] * scale : -1e30f;
            float bsc = okB ? sB[i] * scale : -1e30f;
            float mt = fmaxf(a, bsc);
#pragma unroll
            for (int off = 16; off; off >>= 1)
                mt = fmaxf(mt, __shfl_xor_sync(0xffffffffu, mt, off));
            float mn = fmaxf(m_i[i], mt);
            float fac = __expf(m_i[i] - mn);
            float pA = __expf(a - mn);
            float pB = __expf(bsc - mn);
            float rs = pA + pB;
#pragma unroll
            for (int off = 16; off; off >>= 1)
                rs += __shfl_xor_sync(0xffffffffu, rs, off);
            l_i[i] = l_i[i] * fac + rs;
            o0[i] *= fac;
            o1[i] *= fac;
            m_i[i] = mn;
            *(float2*)&Ss[(warp * 8 + i) * P + c0] = make_float2(pA, pB);
        }
        __syncwarp();   // each warp reads only the rows it wrote

        // O += P @ V (O cols c0, c0+1 over head dim)
#pragma unroll 16
        for (int s = 0; s < 64; ++s) {
            float2 vv = *(const float2*)&Vs[s * P + c0];
            const float* prow = &Ss[(warp * 8) * P + s];
#pragma unroll
            for (int i = 0; i < 8; ++i) {
                float p = prow[i * P];
                o0[i] = fmaf(p, vv.x, o0[i]);
                o1[i] = fmaf(p, vv.y, o1[i]);
            }
        }
    }

    // write y (B,T,C) layout
#pragma unroll
    for (int i = 0; i < 8; ++i) {
        int t = t0 + warp * 8 + i;
        if (t < TT) {
            float inv = 1.f / l_i[i];
            *(float2*)&y[((size_t)(b * TT + t)) * CC + h * DD + c0] =
                make_float2(o0[i] * inv, o1[i] * inv);
        }
    }
}

// ---------------------------------------------------------------------------
extern "C" void kernel_launch(void* const* d_in, const int* in_sizes, int n_in,
                              void* d_out, int out_size)
{
    const float* x      = (const float*)d_in[0];
    const float* W_attn = (const float*)d_in[1];
    const float* W_proj = (const float*)d_in[2];
    float* out = (float*)d_out;

    float* qkv = nullptr;
    float* y = nullptr;
    cudaGetSymbolAddress((void**)&qkv, g_qkv);
    cudaGetSymbolAddress((void**)&y, g_y);

    // 1) qkv = x @ W_attn : (8196 x 3072), K = 1024
    {
        dim3 grid(QKV_COLS / 128, (MROWS + 127) / 128);
        sgemm_kernel<<<grid, 256>>>(x, W_attn, qkv, MROWS, QKV_COLS, CC);
    }

    // 2) attention -> y (B,T,C)
    {
        const int smemBytes = 4 * 64 * 66 * (int)sizeof(float);  // 67584
        cudaFuncSetAttribute(attn_kernel,
                             cudaFuncAttributeMaxDynamicSharedMemorySize,
                             smemBytes);
        dim3 grid((TT + 63) / 64, BB * HH);   // (33, 64)
        attn_kernel<<<grid, 256, smemBytes>>>(qkv, y);
    }

    // 3) out = y @ W_proj : (8196 x 1024), K = 1024
    {
        dim3 grid(CC / 128, (MROWS + 127) / 128);
        sgemm_kernel<<<grid, 256>>>(y, W_proj, out, MROWS, CC, CC);
    }
}

// round 3
// speedup vs baseline: 1.6285x; 1.6285x over previous
#include <cuda_runtime.h>
#include <math.h>
#include <stdint.h>

// Problem constants
#define BB 4
#define TT 2049
#define CC 1024
#define HH 16
#define DD 64
#define MROWS (BB*TT)          // 8196
#define QKV_COLS (3*CC)        // 3072

// Scratch (device globals: allocation-free, graph-capturable)
__device__ float g_qkv[(size_t)MROWS * QKV_COLS];   // (B*T, 3C)
__device__ float g_y[(size_t)MROWS * CC];           // (B*T, C)
__device__ float g_wt_attn[(size_t)QKV_COLS * CC];  // W_attn^T : [N=3072][K=1024]
__device__ float g_wt_proj[(size_t)CC * CC];        // W_proj^T : [N=1024][K=1024]

// ---------------------------------------------------------------------------
// helpers
// ---------------------------------------------------------------------------
__device__ __forceinline__ uint32_t smem_u32(const void* p) {
    uint32_t a;
    asm("{ .reg .u64 t; cvta.to.shared.u64 t, %1; cvt.u32.u64 %0, t; }" : "=r"(a) : "l"(p));
    return a;
}
__device__ __forceinline__ void cp16(uint32_t s, const void* g) {
    asm volatile("cp.async.cg.shared.global [%0], [%1], 16;" :: "r"(s), "l"(g));
}
__device__ __forceinline__ void cp_commit() {
    asm volatile("cp.async.commit_group;" ::: "memory");
}
__device__ __forceinline__ void cp_wait1() {
    asm volatile("cp.async.wait_group 1;" ::: "memory");
}
__device__ __forceinline__ uint32_t f2tf32(float f) {
    uint32_t u;
    asm("cvt.rna.tf32.f32 %0, %1;" : "=r"(u) : "f"(f));
    return u;
}
__device__ __forceinline__ void mma_tf32(float* d, const uint32_t* a, const uint32_t* b) {
    asm volatile(
        "mma.sync.aligned.m16n8k8.row.col.f32.tf32.tf32.f32 "
        "{%0,%1,%2,%3}, {%4,%5,%6,%7}, {%8,%9}, {%0,%1,%2,%3};"
        : "+f"(d[0]), "+f"(d[1]), "+f"(d[2]), "+f"(d[3])
        : "r"(a[0]), "r"(a[1]), "r"(a[2]), "r"(a[3]), "r"(b[0]), "r"(b[1]));
}

// ---------------------------------------------------------------------------
// Transpose: out[c][r] = in[r][c].  in: R x Ccols (row-major). R,Ccols % 32 == 0.
// ---------------------------------------------------------------------------
__global__ __launch_bounds__(256) void transpose_kernel(
    const float* __restrict__ in, float* __restrict__ out, int R, int Ccols)
{
    __shared__ float t[32][33];
    int x = blockIdx.x * 32 + threadIdx.x;
    int y0 = blockIdx.y * 32;
#pragma unroll
    for (int j = threadIdx.y; j < 32; j += 8)
        t[j][threadIdx.x] = in[(size_t)(y0 + j) * Ccols + x];
    __syncthreads();
    int ox = y0 + threadIdx.x;
    int oy0 = blockIdx.x * 32;
#pragma unroll
    for (int j = threadIdx.y; j < 32; j += 8)
        out[(size_t)(oy0 + j) * R + ox] = t[threadIdx.x][j];
}

// ---------------------------------------------------------------------------
// TF32 tensor-core GEMM via mma.sync: C(MxN) = A(MxK) @ Bt(NxK)^T, fp32 I/O.
// 128x128 CTA tile, BK=16, 256 threads (8 warps: 2M x 4N), warp tile 64x32.
// Requires N%128==0, K%16==0. M guarded.
// ---------------------------------------------------------------------------
#define GPITCH 20   // smem row pitch in floats (16 data + 4 pad), conflict-free

__global__ __launch_bounds__(256) void tc_gemm_kernel(
    const float* __restrict__ A, const float* __restrict__ Bt,
    float* __restrict__ C, int M, int N, int K)
{
    __shared__ float As[2][128 * GPITCH];
    __shared__ float Bs[2][128 * GPITCH];

    const int tid  = threadIdx.x;
    const int warp = tid >> 5;
    const int lane = tid & 31;
    const int wm = warp >> 2;          // 0..1
    const int wn = warp & 3;           // 0..3
    const int g  = lane >> 2;          // 0..7
    const int tq = lane & 3;           // 0..3

    const int bm = blockIdx.y * 128;
    const int bn = blockIdx.x * 128;
    const int NT = K >> 4;

    // global->smem loader: 128 rows x 16 floats, one float4 per (thread,i)
    const int ldRow = tid >> 2;        // 0..63
    const int ldC4  = (tid & 3) << 2;  // 0,4,8,12
    int aRow0 = bm + ldRow;       if (aRow0 >= M) aRow0 = M - 1;
    int aRow1 = bm + ldRow + 64;  if (aRow1 >= M) aRow1 = M - 1;
    const float* aSrc0 = A  + (size_t)aRow0 * K + ldC4;
    const float* aSrc1 = A  + (size_t)aRow1 * K + ldC4;
    const float* bSrc0 = Bt + (size_t)(bn + ldRow) * K + ldC4;
    const float* bSrc1 = Bt + (size_t)(bn + ldRow + 64) * K + ldC4;

    uint32_t aDst[2], bDst[2];
#pragma unroll
    for (int s = 0; s < 2; ++s) {
        aDst[s] = smem_u32(&As[s][ldRow * GPITCH + ldC4]);
        bDst[s] = smem_u32(&Bs[s][ldRow * GPITCH + ldC4]);
    }
    const uint32_t rowStep = 64 * GPITCH * 4;  // bytes for +64 rows

    auto load_stage = [&](int s, int k0) {
        cp16(aDst[s],           aSrc0 + k0);
        cp16(aDst[s] + rowStep, aSrc1 + k0);
        cp16(bDst[s],           bSrc0 + k0);
        cp16(bDst[s] + rowStep, bSrc1 + k0);
    };

    float acc[4][4][4];
#pragma unroll
    for (int i = 0; i < 4; ++i)
#pragma unroll
        for (int j = 0; j < 4; ++j)
#pragma unroll
            for (int r = 0; r < 4; ++r) acc[i][j][r] = 0.f;

    // prologue
    load_stage(0, 0);
    cp_commit();
    if (NT > 1) load_stage(1, 16);
    cp_commit();

    for (int kt = 0; kt < NT; ++kt) {
        const int buf = kt & 1;
        cp_wait1();
        __syncthreads();

        const float* as = As[buf];
        const float* bs = Bs[buf];
#pragma unroll
        for (int ks = 0; ks < 2; ++ks) {
            const int kc = ks * 8 + tq;
            uint32_t af[4][4], bf[4][2];
#pragma unroll
            for (int im = 0; im < 4; ++im) {
                const float* p = &as[(wm * 64 + im * 16 + g) * GPITCH + kc];
                af[im][0] = f2tf32(p[0]);
                af[im][1] = f2tf32(p[8 * GPITCH]);
                af[im][2] = f2tf32(p[4]);
                af[im][3] = f2tf32(p[8 * GPITCH + 4]);
            }
#pragma unroll
            for (int jn = 0; jn < 4; ++jn) {
                const float* p = &bs[(wn * 32 + jn * 8 + g) * GPITCH + kc];
                bf[jn][0] = f2tf32(p[0]);
                bf[jn][1] = f2tf32(p[4]);
            }
#pragma unroll
            for (int im = 0; im < 4; ++im)
#pragma unroll
                for (int jn = 0; jn < 4; ++jn)
                    mma_tf32(acc[im][jn], af[im], bf[jn]);
        }
        __syncthreads();

        const int cn = kt + 2;
        if (cn < NT) load_stage(buf, cn << 4);
        cp_commit();
    }

    // epilogue
#pragma unroll
    for (int im = 0; im < 4; ++im) {
        const int r0 = bm + wm * 64 + im * 16 + g;
#pragma unroll
        for (int jn = 0; jn < 4; ++jn) {
            const int cc = bn + wn * 32 + jn * 8 + tq * 2;
            if (r0 < M)
                *(float2*)&C[(size_t)r0 * N + cc] =
                    make_float2(acc[im][jn][0], acc[im][jn][1]);
            if (r0 + 8 < M)
                *(float2*)&C[(size_t)(r0 + 8) * N + cc] =
                    make_float2(acc[im][jn][2], acc[im][jn][3]);
        }
    }
}

// ---------------------------------------------------------------------------
// Flash attention (fp32, online softmax) — unchanged.
// ---------------------------------------------------------------------------
__global__ __launch_bounds__(256) void attn_kernel(
    const float* __restrict__ qkv, float* __restrict__ y)
{
    extern __shared__ float sm[];
    const int P = 66;
    float* Qs = sm;
    float* Kt = sm + 64 * P;
    float* Vs = sm + 2 * 64 * P;
    float* Ss = sm + 3 * 64 * P;

    const int tid  = threadIdx.x;
    const int warp = tid >> 5;
    const int lane = tid & 31;
    const int qt = blockIdx.x;
    const int bh = blockIdx.y;
    const int b = bh >> 4, h = bh & 15;
    const int t0 = qt * 64;

    const size_t rowStride = QKV_COLS;
    const float* qbase = qkv + (size_t)b * TT * rowStride + h * DD;
    const float* kbase = qbase + CC;
    const float* vbase = qbase + 2 * CC;

    for (int idx = tid; idx < 64 * DD; idx += 256) {
        int r = idx >> 6, c = idx & 63;
        int t = t0 + r;
        Qs[r * P + c] = (t < TT) ? qbase[(size_t)t * rowStride + c] : 0.f;
    }

    const float scale = 0.125f;
    const int c0 = lane * 2;

    float m_i[8], l_i[8], o0[8], o1[8];
#pragma unroll
    for (int i = 0; i < 8; ++i) { m_i[i] = -INFINITY; l_i[i] = 0.f; o0[i] = 0.f; o1[i] = 0.f; }

    const int nk = (qt == 0) ? ((TT + 63) >> 6) : (qt + 1);

    for (int kt = 0; kt < nk; ++kt) {
        const int s0 = kt * 64;
        __syncthreads();
        for (int idx = tid; idx < 64 * DD; idx += 256) {
            int r = idx >> 6, c = idx & 63;
            int s = s0 + r;
            float kk = (s < TT) ? kbase[(size_t)s * rowStride + c] : 0.f;
            float vv = (s < TT) ? vbase[(size_t)s * rowStride + c] : 0.f;
            Kt[c * P + r] = kk;
            Vs[r * P + c] = vv;
        }
        __syncthreads();

        float sA[8], sB[8];
#pragma unroll
        for (int i = 0; i < 8; ++i) { sA[i] = 0.f; sB[i] = 0.f; }
#pragma unroll 16
        for (int d = 0; d < DD; ++d) {
            float2 kk = *(const float2*)&Kt[d * P + c0];
            const float* qrow = &Qs[(warp * 8) * P + d];
#pragma unroll
            for (int i = 0; i < 8; ++i) {
                float q = qrow[i * P];
                sA[i] = fmaf(q, kk.x, sA[i]);
                sB[i] = fmaf(q, kk.y, sB[i]);
            }
        }

#pragma unroll
        for (int i = 0; i < 8; ++i) {
            int t = t0 + warp * 8 + i;
            int sIdxA = s0 + c0, sIdxB = sIdxA + 1;
            bool okA = (sIdxA < TT) && (sIdxA <= t || t == 0);
            bool okB = (sIdxB < TT) && (sIdxB <= t || t == 0);
            float a = okA ? sA[i] * scale : -1e30f;
            float bsc = okB ? sB[i] * scale : -1e30f;
            float mt = fmaxf(a, bsc);
#pragma unroll
            for (int off = 16; off; off >>= 1)
                mt = fmaxf(mt, __shfl_xor_sync(0xffffffffu, mt, off));
            float mn = fmaxf(m_i[i], mt);
            float fac = __expf(m_i[i] - mn);
            float pA = __expf(a - mn);
            float pB = __expf(bsc - mn);
            float rs = pA + pB;
#pragma unroll
            for (int off = 16; off; off >>= 1)
                rs += __shfl_xor_sync(0xffffffffu, rs, off);
            l_i[i] = l_i[i] * fac + rs;
            o0[i] *= fac;
            o1[i] *= fac;
            m_i[i] = mn;
            *(float2*)&Ss[(warp * 8 + i) * P + c0] = make_float2(pA, pB);
        }
        __syncwarp();

#pragma unroll 16
        for (int s = 0; s < 64; ++s) {
            float2 vv = *(const float2*)&Vs[s * P + c0];
            const float* prow = &Ss[(warp * 8) * P + s];
#pragma unroll
            for (int i = 0; i < 8; ++i) {
                float p = prow[i * P];
                o0[i] = fmaf(p, vv.x, o0[i]);
                o1[i] = fmaf(p, vv.y, o1[i]);
            }
        }
    }

#pragma unroll
    for (int i = 0; i < 8; ++i) {
        int t = t0 + warp * 8 + i;
        if (t < TT) {
            float inv = 1.f / l_i[i];
            *(float2*)&y[((size_t)(b * TT + t)) * CC + h * DD + c0] =
                make_float2(o0[i] * inv, o1[i] * inv);
        }
    }
}

// ---------------------------------------------------------------------------
extern "C" void kernel_launch(void* const* d_in, const int* in_sizes, int n_in,
                              void* d_out, int out_size)
{
    const float* x      = (const float*)d_in[0];
    const float* W_attn = (const float*)d_in[1];
    const float* W_proj = (const float*)d_in[2];
    float* out = (float*)d_out;

    float *qkv = nullptr, *y = nullptr, *wt_attn = nullptr, *wt_proj = nullptr;
    cudaGetSymbolAddress((void**)&qkv, g_qkv);
    cudaGetSymbolAddress((void**)&y, g_y);
    cudaGetSymbolAddress((void**)&wt_attn, g_wt_attn);
    cudaGetSymbolAddress((void**)&wt_proj, g_wt_proj);

    // 0) transpose weights: Wt[n][k] = W[k][n]
    {
        dim3 blk(32, 8);
        transpose_kernel<<<dim3(QKV_COLS / 32, CC / 32), blk>>>(W_attn, wt_attn, CC, QKV_COLS);
        transpose_kernel<<<dim3(CC / 32, CC / 32), blk>>>(W_proj, wt_proj, CC, CC);
    }

    // 1) qkv = x @ W_attn : (8196 x 3072), K = 1024  (tf32 mma.sync)
    {
        dim3 grid(QKV_COLS / 128, (MROWS + 127) / 128);
        tc_gemm_kernel<<<grid, 256>>>(x, wt_attn, qkv, MROWS, QKV_COLS, CC);
    }

    // 2) attention -> y (B,T,C)
    {
        const int smemBytes = 4 * 64 * 66 * (int)sizeof(float);
        cudaFuncSetAttribute(attn_kernel,
                             cudaFuncAttributeMaxDynamicSharedMemorySize, smemBytes);
        dim3 grid((TT + 63) / 64, BB * HH);
        attn_kernel<<<grid, 256, smemBytes>>>(qkv, y);
    }

    // 3) out = y @ W_proj : (8196 x 1024), K = 1024  (tf32 mma.sync)
    {
        dim3 grid(CC / 128, (MROWS + 127) / 128);
        tc_gemm_kernel<<<grid, 256>>>(y, wt_proj, out, MROWS, CC, CC);
    }
}

// round 4
// speedup vs baseline: 2.9873x; 1.8344x over previous
#include <cuda_runtime.h>
#include <cuda_bf16.h>
#include <math.h>
#include <stdint.h>

// Problem constants
#define BB 4
#define TT 2049
#define CC 1024
#define HH 16
#define DD 64
#define MROWS (BB*TT)          // 8196
#define QKV_COLS (3*CC)        // 3072

// Scratch (device globals: allocation-free, graph-capturable)
__device__ float g_qkv[(size_t)MROWS * QKV_COLS];   // (B*T, 3C) fp32
__device__ float g_y[(size_t)MROWS * CC];           // (B*T, C)  fp32
__device__ float g_wt_attn[(size_t)QKV_COLS * CC];  // W_attn^T
__device__ float g_wt_proj[(size_t)CC * CC];        // W_proj^T
__device__ __nv_bfloat16 g_qkv_hi[(size_t)MROWS * QKV_COLS];
__device__ __nv_bfloat16 g_qkv_lo[(size_t)MROWS * QKV_COLS];

// ---------------------------------------------------------------------------
// helpers
// ---------------------------------------------------------------------------
__device__ __forceinline__ uint32_t smem_u32(const void* p) {
    uint32_t a;
    asm("{ .reg .u64 t; cvta.to.shared.u64 t, %1; cvt.u32.u64 %0, t; }" : "=r"(a) : "l"(p));
    return a;
}
__device__ __forceinline__ void cp16(uint32_t s, const void* g) {
    asm volatile("cp.async.cg.shared.global [%0], [%1], 16;" :: "r"(s), "l"(g));
}
__device__ __forceinline__ void cp_commit() {
    asm volatile("cp.async.commit_group;" ::: "memory");
}
__device__ __forceinline__ void cp_wait1() {
    asm volatile("cp.async.wait_group 1;" ::: "memory");
}
__device__ __forceinline__ uint32_t f2tf32(float f) {
    uint32_t u;
    asm("cvt.rna.tf32.f32 %0, %1;" : "=r"(u) : "f"(f));
    return u;
}
__device__ __forceinline__ void mma_tf32(float* d, const uint32_t* a, const uint32_t* b) {
    asm volatile(
        "mma.sync.aligned.m16n8k8.row.col.f32.tf32.tf32.f32 "
        "{%0,%1,%2,%3}, {%4,%5,%6,%7}, {%8,%9}, {%0,%1,%2,%3};"
        : "+f"(d[0]), "+f"(d[1]), "+f"(d[2]), "+f"(d[3])
        : "r"(a[0]), "r"(a[1]), "r"(a[2]), "r"(a[3]), "r"(b[0]), "r"(b[1]));
}
__device__ __forceinline__ void mma_bf16(float* d, const uint32_t* a, uint32_t b0, uint32_t b1) {
    asm volatile(
        "mma.sync.aligned.m16n8k16.row.col.f32.bf16.bf16.f32 "
        "{%0,%1,%2,%3}, {%4,%5,%6,%7}, {%8,%9}, {%0,%1,%2,%3};"
        : "+f"(d[0]), "+f"(d[1]), "+f"(d[2]), "+f"(d[3])
        : "r"(a[0]), "r"(a[1]), "r"(a[2]), "r"(a[3]), "r"(b0), "r"(b1));
}
__device__ __forceinline__ void ldm4(uint32_t& r0, uint32_t& r1, uint32_t& r2, uint32_t& r3,
                                     uint32_t a) {
    asm volatile("ldmatrix.sync.aligned.m8n8.x4.shared.b16 {%0,%1,%2,%3}, [%4];"
                 : "=r"(r0), "=r"(r1), "=r"(r2), "=r"(r3) : "r"(a));
}
__device__ __forceinline__ void ldm4t(uint32_t& r0, uint32_t& r1, uint32_t& r2, uint32_t& r3,
                                      uint32_t a) {
    asm volatile("ldmatrix.sync.aligned.m8n8.x4.trans.shared.b16 {%0,%1,%2,%3}, [%4];"
                 : "=r"(r0), "=r"(r1), "=r"(r2), "=r"(r3) : "r"(a));
}
// split two fp32 into packed bf16 hi + lo (low half = p0)
__device__ __forceinline__ void pack_hilo(float p0, float p1, uint32_t& hi, uint32_t& lo) {
    uint32_t hh;
    asm("cvt.rn.bf16x2.f32 %0, %1, %2;" : "=r"(hh) : "f"(p1), "f"(p0));
    float h0 = __uint_as_float(hh << 16);
    float h1 = __uint_as_float(hh & 0xffff0000u);
    float l0 = p0 - h0, l1 = p1 - h1;
    uint32_t ll;
    asm("cvt.rn.bf16x2.f32 %0, %1, %2;" : "=r"(ll) : "f"(l1), "f"(l0));
    hi = hh; lo = ll;
}

// ---------------------------------------------------------------------------
// Transpose: out[c][r] = in[r][c]
// ---------------------------------------------------------------------------
__global__ __launch_bounds__(256) void transpose_kernel(
    const float* __restrict__ in, float* __restrict__ out, int R, int Ccols)
{
    __shared__ float t[32][33];
    int x = blockIdx.x * 32 + threadIdx.x;
    int y0 = blockIdx.y * 32;
#pragma unroll
    for (int j = threadIdx.y; j < 32; j += 8)
        t[j][threadIdx.x] = in[(size_t)(y0 + j) * Ccols + x];
    __syncthreads();
    int ox = y0 + threadIdx.x;
    int oy0 = blockIdx.x * 32;
#pragma unroll
    for (int j = threadIdx.y; j < 32; j += 8)
        out[(size_t)(oy0 + j) * R + ox] = t[threadIdx.x][j];
}

// ---------------------------------------------------------------------------
// Convert qkv fp32 -> bf16 hi/lo, scaling Q columns by 1/sqrt(D)
// ---------------------------------------------------------------------------
__global__ __launch_bounds__(256) void convert_qkv_kernel(
    const float* __restrict__ qkv, __nv_bfloat16* __restrict__ hi,
    __nv_bfloat16* __restrict__ lo)
{
    size_t idx = (size_t)blockIdx.x * 256 + threadIdx.x;   // pair index
    size_t i2 = idx * 2;
    int col = (int)(i2 % QKV_COLS);
    float scale = (col < CC) ? 0.125f : 1.0f;
    float2 v = *(const float2*)(qkv + i2);
    v.x *= scale; v.y *= scale;
    uint32_t h, l;
    pack_hilo(v.x, v.y, h, l);
    ((uint32_t*)hi)[idx] = h;
    ((uint32_t*)lo)[idx] = l;
}

// ---------------------------------------------------------------------------
// TF32 tensor-core GEMM (unchanged from round 3)
// ---------------------------------------------------------------------------
#define GPITCH 20

__global__ __launch_bounds__(256) void tc_gemm_kernel(
    const float* __restrict__ A, const float* __restrict__ Bt,
    float* __restrict__ C, int M, int N, int K)
{
    __shared__ float As[2][128 * GPITCH];
    __shared__ float Bs[2][128 * GPITCH];

    const int tid  = threadIdx.x;
    const int warp = tid >> 5;
    const int lane = tid & 31;
    const int wm = warp >> 2;
    const int wn = warp & 3;
    const int g  = lane >> 2;
    const int tq = lane & 3;

    const int bm = blockIdx.y * 128;
    const int bn = blockIdx.x * 128;
    const int NT = K >> 4;

    const int ldRow = tid >> 2;
    const int ldC4  = (tid & 3) << 2;
    int aRow0 = bm + ldRow;       if (aRow0 >= M) aRow0 = M - 1;
    int aRow1 = bm + ldRow + 64;  if (aRow1 >= M) aRow1 = M - 1;
    const float* aSrc0 = A  + (size_t)aRow0 * K + ldC4;
    const float* aSrc1 = A  + (size_t)aRow1 * K + ldC4;
    const float* bSrc0 = Bt + (size_t)(bn + ldRow) * K + ldC4;
    const float* bSrc1 = Bt + (size_t)(bn + ldRow + 64) * K + ldC4;

    uint32_t aDst[2], bDst[2];
#pragma unroll
    for (int s = 0; s < 2; ++s) {
        aDst[s] = smem_u32(&As[s][ldRow * GPITCH + ldC4]);
        bDst[s] = smem_u32(&Bs[s][ldRow * GPITCH + ldC4]);
    }
    const uint32_t rowStep = 64 * GPITCH * 4;

    auto load_stage = [&](int s, int k0) {
        cp16(aDst[s],           aSrc0 + k0);
        cp16(aDst[s] + rowStep, aSrc1 + k0);
        cp16(bDst[s],           bSrc0 + k0);
        cp16(bDst[s] + rowStep, bSrc1 + k0);
    };

    float acc[4][4][4];
#pragma unroll
    for (int i = 0; i < 4; ++i)
#pragma unroll
        for (int j = 0; j < 4; ++j)
#pragma unroll
            for (int r = 0; r < 4; ++r) acc[i][j][r] = 0.f;

    load_stage(0, 0);
    cp_commit();
    if (NT > 1) load_stage(1, 16);
    cp_commit();

    for (int kt = 0; kt < NT; ++kt) {
        const int buf = kt & 1;
        cp_wait1();
        __syncthreads();

        const float* as = As[buf];
        const float* bs = Bs[buf];
#pragma unroll
        for (int ks = 0; ks < 2; ++ks) {
            const int kc = ks * 8 + tq;
            uint32_t af[4][4], bf[4][2];
#pragma unroll
            for (int im = 0; im < 4; ++im) {
                const float* p = &as[(wm * 64 + im * 16 + g) * GPITCH + kc];
                af[im][0] = f2tf32(p[0]);
                af[im][1] = f2tf32(p[8 * GPITCH]);
                af[im][2] = f2tf32(p[4]);
                af[im][3] = f2tf32(p[8 * GPITCH + 4]);
            }
#pragma unroll
            for (int jn = 0; jn < 4; ++jn) {
                const float* p = &bs[(wn * 32 + jn * 8 + g) * GPITCH + kc];
                bf[jn][0] = f2tf32(p[0]);
                bf[jn][1] = f2tf32(p[4]);
            }
#pragma unroll
            for (int im = 0; im < 4; ++im)
#pragma unroll
                for (int jn = 0; jn < 4; ++jn)
                    mma_tf32(acc[im][jn], af[im], bf[jn]);
        }
        __syncthreads();

        const int cn = kt + 2;
        if (cn < NT) load_stage(buf, cn << 4);
        cp_commit();
    }

#pragma unroll
    for (int im = 0; im < 4; ++im) {
        const int r0 = bm + wm * 64 + im * 16 + g;
#pragma unroll
        for (int jn = 0; jn < 4; ++jn) {
            const int cc = bn + wn * 32 + jn * 8 + tq * 2;
            if (r0 < M)
                *(float2*)&C[(size_t)r0 * N + cc] =
                    make_float2(acc[im][jn][0], acc[im][jn][1]);
            if (r0 + 8 < M)
                *(float2*)&C[(size_t)(r0 + 8) * N + cc] =
                    make_float2(acc[im][jn][2], acc[im][jn][3]);
        }
    }
}

// ---------------------------------------------------------------------------
// Tensor-core flash attention (bf16x3 split, fp32 softmax).
// CTA = 128 q-rows x one (b,h). 8 warps, each m16. Key tiles of 64.
// smem: Q hi/lo [128][72]bf16 ; 2-stage { K hi/lo, V hi/lo [64][72] }.
// ---------------------------------------------------------------------------
#define AP 72                       // bf16 pitch (144 bytes/row)
#define QBYTES (128 * AP * 2)       // 18432
#define TBYTES (64 * AP * 2)        // 9216
#define STAGEB (4 * TBYTES)         // 36864
#define ATT_SMEM (2 * QBYTES + 2 * STAGEB)   // 110592

__global__ __launch_bounds__(256) void attn_tc_kernel(
    const __nv_bfloat16* __restrict__ qh_g, const __nv_bfloat16* __restrict__ ql_g,
    float* __restrict__ y)
{
    extern __shared__ char asmem[];
    const uint32_t sb = smem_u32(asmem);
    const uint32_t Qh = sb, Ql = sb + QBYTES;
    const uint32_t KV = sb + 2 * QBYTES;

    const int tid = threadIdx.x, warp = tid >> 5, lane = tid & 31;
    const int g = lane >> 2, tq = lane & 3;
    const int qt = blockIdx.x, bh = blockIdx.y;
    const int b = bh >> 4, h = bh & 15;
    const int t0 = qt * 128;
    int nk = (qt == 0) ? 33 : (2 * qt + 2);
    if (nk > 33) nk = 33;

    const __nv_bfloat16* qsrc_h = qh_g + (size_t)b * TT * QKV_COLS + h * 64;
    const __nv_bfloat16* qsrc_l = ql_g + (size_t)b * TT * QKV_COLS + h * 64;
    const __nv_bfloat16* src_h[4] = { qsrc_h + CC, qsrc_l + CC,      // K hi, K lo
                                      qsrc_h + 2*CC, qsrc_l + 2*CC };// V hi, V lo

    // ---- load Q tile (hi, lo) ----
#pragma unroll
    for (int i = 0; i < 4; ++i) {
        int u = tid + (i << 8);
        int r = u >> 3, dg = u & 7;
        int t = t0 + r; if (t >= TT) t = TT - 1;
        cp16(Qh + r * 144 + dg * 16, qsrc_h + (size_t)t * QKV_COLS + dg * 8);
    }
#pragma unroll
    for (int i = 0; i < 4; ++i) {
        int u = tid + (i << 8);
        int r = u >> 3, dg = u & 7;
        int t = t0 + r; if (t >= TT) t = TT - 1;
        cp16(Ql + r * 144 + dg * 16, qsrc_l + (size_t)t * QKV_COLS + dg * 8);
    }
    cp_commit();

    auto load_kv = [&](int buf, int s0) {
        uint32_t base = KV + buf * STAGEB;
#pragma unroll
        for (int a = 0; a < 4; ++a) {
#pragma unroll
            for (int i = 0; i < 2; ++i) {
                int u = tid + (i << 8);
                int r = u >> 3, dg = u & 7;
                int s = s0 + r; if (s >= TT) s = TT - 1;
                cp16(base + a * TBYTES + r * 144 + dg * 16,
                     src_h[a] + (size_t)s * QKV_COLS + dg * 8);
            }
        }
    };

    load_kv(0, 0);
    cp_commit();
    load_kv(1, 64);
    cp_commit();
    cp_wait1();
    __syncthreads();

    // ---- Q fragments (persist in registers) ----
    const uint32_t qrowoff = (uint32_t)((warp * 16 + (lane & 7) + ((lane >> 3) & 1) * 8) * 144
                                        + ((lane >> 4) & 1) * 16);
    uint32_t qfh[4][4], qfl[4][4];
#pragma unroll
    for (int k = 0; k < 4; ++k) {
        ldm4(qfh[k][0], qfh[k][1], qfh[k][2], qfh[k][3], Qh + qrowoff + k * 32);
        ldm4(qfl[k][0], qfl[k][1], qfl[k][2], qfl[k][3], Ql + qrowoff + k * 32);
    }

    // per-lane ldmatrix offset parts
    const uint32_t krowpart = (uint32_t)(((lane & 7) + ((lane >> 4) & 1) * 8) * 144
                                         + ((lane >> 3) & 1) * 16);
    const uint32_t vrowpart = (uint32_t)(((lane & 7) + ((lane >> 3) & 1) * 8) * 144
                                         + ((lane >> 4) & 1) * 16);

    const int rowA = t0 + warp * 16 + g;
    const int rowB = rowA + 8;
    const int warpRowMin = t0 + warp * 16;

    float mA = -INFINITY, mB = -INFINITY, lA = 0.f, lB = 0.f;
    float o[8][4];
#pragma unroll
    for (int d = 0; d < 8; ++d)
#pragma unroll
        for (int c = 0; c < 4; ++c) o[d][c] = 0.f;

    for (int kt = 0; kt < nk; ++kt) {
        const int buf = kt & 1;
        const int s0 = kt * 64;
        const uint32_t kvb = KV + buf * STAGEB;

        // ---- S = Q K^T ----
        float s[8][4];
#pragma unroll
        for (int j = 0; j < 8; ++j)
#pragma unroll
            for (int c = 0; c < 4; ++c) s[j][c] = 0.f;

#pragma unroll
        for (int k = 0; k < 4; ++k) {
            uint32_t kh[8][2], kl[8][2];
#pragma unroll
            for (int j = 0; j < 4; ++j) {
                uint32_t a = kvb + (uint32_t)(16 * j * 144) + krowpart + k * 32;
                ldm4(kh[2*j][0], kh[2*j][1], kh[2*j+1][0], kh[2*j+1][1], a);
                ldm4(kl[2*j][0], kl[2*j][1], kl[2*j+1][0], kl[2*j+1][1], a + TBYTES);
            }
#pragma unroll
            for (int jn = 0; jn < 8; ++jn) {
                mma_bf16(s[jn], qfh[k], kh[jn][0], kh[jn][1]);
                mma_bf16(s[jn], qfh[k], kl[jn][0], kl[jn][1]);
                mma_bf16(s[jn], qfl[k], kh[jn][0], kh[jn][1]);
            }
        }

        // ---- mask ----
        const bool need_mask = (s0 + 63 > warpRowMin) || (s0 + 63 >= TT);
        if (need_mask) {
#pragma unroll
            for (int jn = 0; jn < 8; ++jn) {
                int sc = s0 + 8 * jn + 2 * tq;
#pragma unroll
                for (int c = 0; c < 4; ++c) {
                    int sidx = sc + (c & 1);
                    int t = (c < 2) ? rowA : rowB;
                    bool ok = (sidx < TT) && (sidx <= t || t == 0);
                    if (!ok) s[jn][c] = -1e30f;
                }
            }
        }

        // ---- online softmax ----
        float tmA = -1e30f, tmB = -1e30f;
#pragma unroll
        for (int jn = 0; jn < 8; ++jn) {
            tmA = fmaxf(tmA, fmaxf(s[jn][0], s[jn][1]));
            tmB = fmaxf(tmB, fmaxf(s[jn][2], s[jn][3]));
        }
        tmA = fmaxf(tmA, __shfl_xor_sync(0xffffffffu, tmA, 1));
        tmA = fmaxf(tmA, __shfl_xor_sync(0xffffffffu, tmA, 2));
        tmB = fmaxf(tmB, __shfl_xor_sync(0xffffffffu, tmB, 1));
        tmB = fmaxf(tmB, __shfl_xor_sync(0xffffffffu, tmB, 2));

        float mAn = fmaxf(mA, tmA), mBn = fmaxf(mB, tmB);
        float facA = __expf(mA - mAn), facB = __expf(mB - mBn);
        mA = mAn; mB = mBn;

        float sumA = 0.f, sumB = 0.f;
#pragma unroll
        for (int jn = 0; jn < 8; ++jn) {
            s[jn][0] = __expf(s[jn][0] - mAn);
            s[jn][1] = __expf(s[jn][1] - mAn);
            s[jn][2] = __expf(s[jn][2] - mBn);
            s[jn][3] = __expf(s[jn][3] - mBn);
            sumA += s[jn][0] + s[jn][1];
            sumB += s[jn][2] + s[jn][3];
        }
        sumA += __shfl_xor_sync(0xffffffffu, sumA, 1);
        sumA += __shfl_xor_sync(0xffffffffu, sumA, 2);
        sumB += __shfl_xor_sync(0xffffffffu, sumB, 1);
        sumB += __shfl_xor_sync(0xffffffffu, sumB, 2);

        lA = lA * facA + sumA;
        lB = lB * facB + sumB;
#pragma unroll
        for (int d = 0; d < 8; ++d) {
            o[d][0] *= facA; o[d][1] *= facA;
            o[d][2] *= facB; o[d][3] *= facB;
        }

        // ---- pack P (A-fragments for PV) ----
        uint32_t ph[4][4], pl[4][4];
#pragma unroll
        for (int k = 0; k < 4; ++k) {
            pack_hilo(s[2*k][0],   s[2*k][1],   ph[k][0], pl[k][0]);
            pack_hilo(s[2*k][2],   s[2*k][3],   ph[k][1], pl[k][1]);
            pack_hilo(s[2*k+1][0], s[2*k+1][1], ph[k][2], pl[k][2]);
            pack_hilo(s[2*k+1][2], s[2*k+1][3], ph[k][3], pl[k][3]);
        }

        // ---- O += P V ----
#pragma unroll
        for (int k = 0; k < 4; ++k) {
            const uint32_t vbase = kvb + 2 * TBYTES + (uint32_t)(16 * k * 144) + vrowpart;
#pragma unroll
            for (int jd = 0; jd < 4; ++jd) {
                uint32_t vh0, vh1, vh2, vh3, vl0, vl1, vl2, vl3;
                ldm4t(vh0, vh1, vh2, vh3, vbase + jd * 32);
                ldm4t(vl0, vl1, vl2, vl3, vbase + jd * 32 + TBYTES);
                mma_bf16(o[2*jd],   ph[k], vh0, vh1);
                mma_bf16(o[2*jd],   ph[k], vl0, vl1);
                mma_bf16(o[2*jd],   pl[k], vh0, vh1);
                mma_bf16(o[2*jd+1], ph[k], vh2, vh3);
                mma_bf16(o[2*jd+1], ph[k], vl2, vl3);
                mma_bf16(o[2*jd+1], pl[k], vh2, vh3);
            }
        }

        __syncthreads();               // done reading buf
        if (kt + 2 < nk) load_kv(buf, (kt + 2) * 64);
        cp_commit();
        cp_wait1();
        __syncthreads();
    }

    // ---- epilogue ----
    if (rowA < TT) {
        float il = 1.f / lA;
        float* dst = y + (size_t)(b * TT + rowA) * CC + h * 64 + tq * 2;
#pragma unroll
        for (int d = 0; d < 8; ++d)
            *(float2*)(dst + d * 8) = make_float2(o[d][0] * il, o[d][1] * il);
    }
    if (rowB < TT) {
        float il = 1.f / lB;
        float* dst = y + (size_t)(b * TT + rowB) * CC + h * 64 + tq * 2;
#pragma unroll
        for (int d = 0; d < 8; ++d)
            *(float2*)(dst + d * 8) = make_float2(o[d][2] * il, o[d][3] * il);
    }
}

// ---------------------------------------------------------------------------
extern "C" void kernel_launch(void* const* d_in, const int* in_sizes, int n_in,
                              void* d_out, int out_size)
{
    const float* x      = (const float*)d_in[0];
    const float* W_attn = (const float*)d_in[1];
    const float* W_proj = (const float*)d_in[2];
    float* out = (float*)d_out;

    float *qkv = nullptr, *y = nullptr, *wt_attn = nullptr, *wt_proj = nullptr;
    __nv_bfloat16 *qkv_hi = nullptr, *qkv_lo = nullptr;
    cudaGetSymbolAddress((void**)&qkv, g_qkv);
    cudaGetSymbolAddress((void**)&y, g_y);
    cudaGetSymbolAddress((void**)&wt_attn, g_wt_attn);
    cudaGetSymbolAddress((void**)&wt_proj, g_wt_proj);
    cudaGetSymbolAddress((void**)&qkv_hi, g_qkv_hi);
    cudaGetSymbolAddress((void**)&qkv_lo, g_qkv_lo);

    // 0) transpose weights
    {
        dim3 blk(32, 8);
        transpose_kernel<<<dim3(QKV_COLS / 32, CC / 32), blk>>>(W_attn, wt_attn, CC, QKV_COLS);
        transpose_kernel<<<dim3(CC / 32, CC / 32), blk>>>(W_proj, wt_proj, CC, CC);
    }

    // 1) qkv = x @ W_attn (tf32 mma)
    {
        dim3 grid(QKV_COLS / 128, (MROWS + 127) / 128);
        tc_gemm_kernel<<<grid, 256>>>(x, wt_attn, qkv, MROWS, QKV_COLS, CC);
    }

    // 2) convert qkv -> bf16 hi/lo (Q pre-scaled by 1/8)
    {
        int nblk = (int)(((size_t)MROWS * QKV_COLS / 2) / 256);
        convert_qkv_kernel<<<nblk, 256>>>(qkv, qkv_hi, qkv_lo);
    }

    // 3) attention -> y (fp32)
    {
        cudaFuncSetAttribute(attn_tc_kernel,
                             cudaFuncAttributeMaxDynamicSharedMemorySize, ATT_SMEM);
        dim3 grid(17, BB * HH);
        attn_tc_kernel<<<grid, 256, ATT_SMEM>>>(qkv_hi, qkv_lo, y);
    }

    // 4) out = y @ W_proj (tf32 mma)
    {
        dim3 grid(CC / 128, (MROWS + 127) / 128);
        tc_gemm_kernel<<<grid, 256>>>(y, wt_proj, out, MROWS, CC, CC);
    }
}

// round 6
// speedup vs baseline: 3.4081x; 1.1408x over previous
#include <cuda_runtime.h>
#include <cuda_bf16.h>
#include <math.h>
#include <stdint.h>

// Problem constants
#define BB 4
#define TT 2049
#define CC 1024
#define HH 16
#define DD 64
#define MROWS (BB*TT)          // 8196
#define QKV_COLS (3*CC)        // 3072

// Scratch (device globals: allocation-free, graph-capturable)
__device__ float g_xr[(size_t)MROWS * CC];          // x, tf32-rounded
__device__ float g_y[(size_t)MROWS * CC];           // attention out (tf32-rounded)
__device__ float g_wt_attn[(size_t)QKV_COLS * CC];  // W_attn^T (tf32-rounded)
__device__ float g_wt_proj[(size_t)CC * CC];        // W_proj^T (tf32-rounded)
__device__ __nv_bfloat16 g_qkv_hi[(size_t)MROWS * QKV_COLS];
__device__ __nv_bfloat16 g_qkv_lo[(size_t)MROWS * QKV_COLS];

// ---------------------------------------------------------------------------
// helpers
// ---------------------------------------------------------------------------
__device__ __forceinline__ uint32_t smem_u32(const void* p) {
    uint32_t a;
    asm("{ .reg .u64 t; cvta.to.shared.u64 t, %1; cvt.u32.u64 %0, t; }" : "=r"(a) : "l"(p));
    return a;
}
__device__ __forceinline__ void cp16(uint32_t s, const void* g) {
    asm volatile("cp.async.cg.shared.global [%0], [%1], 16;" :: "r"(s), "l"(g));
}
__device__ __forceinline__ void cp_commit() {
    asm volatile("cp.async.commit_group;" ::: "memory");
}
__device__ __forceinline__ void cp_wait1() {
    asm volatile("cp.async.wait_group 1;" ::: "memory");
}
__device__ __forceinline__ uint32_t f2tf32(float f) {
    uint32_t u;
    asm("cvt.rna.tf32.f32 %0, %1;" : "=r"(u) : "f"(f));
    return u;
}
__device__ __forceinline__ float rnd_tf32(float f) {
    return __uint_as_float(f2tf32(f));
}
__device__ __forceinline__ void mma_tf32(float* d, const uint32_t* a, uint32_t b0, uint32_t b1) {
    asm volatile(
        "mma.sync.aligned.m16n8k8.row.col.f32.tf32.tf32.f32 "
        "{%0,%1,%2,%3}, {%4,%5,%6,%7}, {%8,%9}, {%0,%1,%2,%3};"
        : "+f"(d[0]), "+f"(d[1]), "+f"(d[2]), "+f"(d[3])
        : "r"(a[0]), "r"(a[1]), "r"(a[2]), "r"(a[3]), "r"(b0), "r"(b1));
}
__device__ __forceinline__ void mma_bf16(float* d, const uint32_t* a, uint32_t b0, uint32_t b1) {
    asm volatile(
        "mma.sync.aligned.m16n8k16.row.col.f32.bf16.bf16.f32 "
        "{%0,%1,%2,%3}, {%4,%5,%6,%7}, {%8,%9}, {%0,%1,%2,%3};"
        : "+f"(d[0]), "+f"(d[1]), "+f"(d[2]), "+f"(d[3])
        : "r"(a[0]), "r"(a[1]), "r"(a[2]), "r"(a[3]), "r"(b0), "r"(b1));
}
__device__ __forceinline__ void ldm4(uint32_t& r0, uint32_t& r1, uint32_t& r2, uint32_t& r3,
                                     uint32_t a) {
    asm volatile("ldmatrix.sync.aligned.m8n8.x4.shared.b16 {%0,%1,%2,%3}, [%4];"
                 : "=r"(r0), "=r"(r1), "=r"(r2), "=r"(r3) : "r"(a));
}
__device__ __forceinline__ void ldm4t(uint32_t& r0, uint32_t& r1, uint32_t& r2, uint32_t& r3,
                                      uint32_t a) {
    asm volatile("ldmatrix.sync.aligned.m8n8.x4.trans.shared.b16 {%0,%1,%2,%3}, [%4];"
                 : "=r"(r0), "=r"(r1), "=r"(r2), "=r"(r3) : "r"(a));
}
// split two fp32 into packed bf16 hi + lo (low half = p0)
__device__ __forceinline__ void pack_hilo(float p0, float p1, uint32_t& hi, uint32_t& lo) {
    uint32_t hh;
    asm("cvt.rn.bf16x2.f32 %0, %1, %2;" : "=r"(hh) : "f"(p1), "f"(p0));
    float h0 = __uint_as_float(hh << 16);
    float h1 = __uint_as_float(hh & 0xffff0000u);
    float l0 = p0 - h0, l1 = p1 - h1;
    uint32_t ll;
    asm("cvt.rn.bf16x2.f32 %0, %1, %2;" : "=r"(ll) : "f"(l1), "f"(l0));
    hi = hh; lo = ll;
}

// ---------------------------------------------------------------------------
// Transpose + tf32 round: out[c][r] = rnd(in[r][c])
// ---------------------------------------------------------------------------
__global__ __launch_bounds__(256) void transpose_kernel(
    const float* __restrict__ in, float* __restrict__ out, int R, int Ccols)
{
    __shared__ float t[32][33];
    int x = blockIdx.x * 32 + threadIdx.x;
    int y0 = blockIdx.y * 32;
#pragma unroll
    for (int j = threadIdx.y; j < 32; j += 8)
        t[j][threadIdx.x] = in[(size_t)(y0 + j) * Ccols + x];
    __syncthreads();
    int ox = y0 + threadIdx.x;
    int oy0 = blockIdx.x * 32;
#pragma unroll
    for (int j = threadIdx.y; j < 32; j += 8)
        out[(size_t)(oy0 + j) * R + ox] = rnd_tf32(t[threadIdx.x][j]);
}

// ---------------------------------------------------------------------------
// Elementwise tf32 round (float4)
// ---------------------------------------------------------------------------
__global__ __launch_bounds__(256) void round_kernel(
    const float* __restrict__ in, float* __restrict__ out, size_t n4)
{
    size_t i = (size_t)blockIdx.x * 256 + threadIdx.x;
    if (i < n4) {
        float4 v = ((const float4*)in)[i];
        v.x = rnd_tf32(v.x); v.y = rnd_tf32(v.y);
        v.z = rnd_tf32(v.z); v.w = rnd_tf32(v.w);
        ((float4*)out)[i] = v;
    }
}

// ---------------------------------------------------------------------------
// TF32 tensor-core GEMM, ldmatrix fragments, pre-rounded inputs.
// C(MxN) = A(MxK) @ Bt(NxK)^T. 128x128 tile, BK=32, 256 thr (2Mx4N warps).
// MODE 0: store fp32 C. MODE 1: store bf16 hi/lo split, Q-scale cols < CC.
// ---------------------------------------------------------------------------
#define P36 36
#define TILEF (128 * P36)            // floats per tile
#define GSMEM (4 * TILEF * 4)        // bytes: 2 stages x (A,B)

template<int MODE>
__global__ __launch_bounds__(256) void tc_gemm2_kernel(
    const float* __restrict__ A, const float* __restrict__ Bt,
    float* __restrict__ Cf, __nv_bfloat16* __restrict__ Chi,
    __nv_bfloat16* __restrict__ Clo, int M, int N, int K)
{
    extern __shared__ float gsm[];
    const uint32_t sb = smem_u32(gsm);
    // stage s: A at s*2*TILEF, B at s*2*TILEF + TILEF (in floats)
    const uint32_t aBase[2] = { sb, sb + 2u * TILEF * 4u };
    const uint32_t bBase[2] = { sb + TILEF * 4u, sb + 3u * TILEF * 4u };

    const int tid  = threadIdx.x;
    const int warp = tid >> 5;
    const int lane = tid & 31;
    const int wm = warp >> 2;          // 0..1
    const int wn = warp & 3;           // 0..3
    const int g  = lane >> 2;
    const int tq = lane & 3;

    const int bm = blockIdx.y * 128;
    const int bn = blockIdx.x * 128;
    const int NT = K >> 5;             // K/32

    // loader: 128 rows x 8 chunks of 16B; thread -> 4 chunks per operand
    const int lr = tid >> 1;                 // unused helper; real mapping below
    (void)lr;

    auto load_stage = [&](int s, int k0) {
#pragma unroll
        for (int i = 0; i < 4; ++i) {
            int u = tid + (i << 8);          // 0..1023
            int r = u >> 3, c = u & 7;
            int ar = bm + r; if (ar >= M) ar = M - 1;
            cp16(aBase[s] + (uint32_t)(r * 144 + c * 16),
                 A + (size_t)ar * K + k0 + c * 4);
        }
#pragma unroll
        for (int i = 0; i < 4; ++i) {
            int u = tid + (i << 8);
            int r = u >> 3, c = u & 7;
            int br = bn + r; if (br >= N) br = N - 1;
            cp16(bBase[s] + (uint32_t)(r * 144 + c * 16),
                 Bt + (size_t)br * K + k0 + c * 4);
        }
    };

    // per-lane ldmatrix offsets
    const int sub = lane >> 3, srow = lane & 7;
    const uint32_t aOff = (uint32_t)((((sub & 1) * 8 + srow) * P36 + (sub >> 1) * 4) * 4);
    const uint32_t bOff = (uint32_t)((((sub >> 1) * 8 + srow) * P36 + (sub & 1) * 4) * 4);

    float acc[4][4][4];
#pragma unroll
    for (int i = 0; i < 4; ++i)
#pragma unroll
        for (int j = 0; j < 4; ++j)
#pragma unroll
            for (int r = 0; r < 4; ++r) acc[i][j][r] = 0.f;

    load_stage(0, 0);
    cp_commit();
    load_stage(1, 32);
    cp_commit();

    for (int kt = 0; kt < NT; ++kt) {
        const int buf = kt & 1;
        cp_wait1();
        __syncthreads();

        const uint32_t aW = aBase[buf] + (uint32_t)(wm * 64 * 144) + aOff;
        const uint32_t bW = bBase[buf] + (uint32_t)(wn * 32 * 144) + bOff;

#pragma unroll
        for (int ks = 0; ks < 4; ++ks) {
            uint32_t af[4][4], bf[2][4];
#pragma unroll
            for (int im = 0; im < 4; ++im)
                ldm4(af[im][0], af[im][1], af[im][2], af[im][3],
                     aW + (uint32_t)(im * 16 * 144) + ks * 32);
#pragma unroll
            for (int jp = 0; jp < 2; ++jp)
                ldm4(bf[jp][0], bf[jp][1], bf[jp][2], bf[jp][3],
                     bW + (uint32_t)(jp * 16 * 144) + ks * 32);
#pragma unroll
            for (int im = 0; im < 4; ++im) {
#pragma unroll
                for (int jn = 0; jn < 4; ++jn)
                    mma_tf32(acc[im][jn], af[im], bf[jn >> 1][(jn & 1) * 2],
                             bf[jn >> 1][(jn & 1) * 2 + 1]);
            }
        }
        __syncthreads();

        const int cn = kt + 2;
        if (cn < NT) load_stage(buf, cn << 5);
        cp_commit();
    }

    // epilogue
#pragma unroll
    for (int im = 0; im < 4; ++im) {
        const int r0 = bm + wm * 64 + im * 16 + g;
#pragma unroll
        for (int jn = 0; jn < 4; ++jn) {
            const int cc = bn + wn * 32 + jn * 8 + tq * 2;
            if (MODE == 0) {
                if (r0 < M)
                    *(float2*)&Cf[(size_t)r0 * N + cc] =
                        make_float2(acc[im][jn][0], acc[im][jn][1]);
                if (r0 + 8 < M)
                    *(float2*)&Cf[(size_t)(r0 + 8) * N + cc] =
                        make_float2(acc[im][jn][2], acc[im][jn][3]);
            } else {
                const float scale = (cc < CC) ? 0.125f : 1.0f;
                if (r0 < M) {
                    uint32_t h, l;
                    pack_hilo(acc[im][jn][0] * scale, acc[im][jn][1] * scale, h, l);
                    size_t o = ((size_t)r0 * N + cc) >> 1;
                    ((uint32_t*)Chi)[o] = h;
                    ((uint32_t*)Clo)[o] = l;
                }
                if (r0 + 8 < M) {
                    uint32_t h, l;
                    pack_hilo(acc[im][jn][2] * scale, acc[im][jn][3] * scale, h, l);
                    size_t o = ((size_t)(r0 + 8) * N + cc) >> 1;
                    ((uint32_t*)Chi)[o] = h;
                    ((uint32_t*)Clo)[o] = l;
                }
            }
        }
    }
}

// ---------------------------------------------------------------------------
// Tensor-core flash attention (bf16x3 split, fp32 softmax).
// CTA = 128 q-rows x one (b,h). 8 warps, each m16. Key tiles of 64.
// ---------------------------------------------------------------------------
#define AP 72
#define QBYTES (128 * AP * 2)
#define TBYTES (64 * AP * 2)
#define STAGEB (4 * TBYTES)
#define ATT_SMEM (2 * QBYTES + 2 * STAGEB)

__global__ __launch_bounds__(256) void attn_tc_kernel(
    const __nv_bfloat16* __restrict__ qh_g, const __nv_bfloat16* __restrict__ ql_g,
    float* __restrict__ y)
{
    extern __shared__ char asmem[];
    const uint32_t sb = smem_u32(asmem);
    const uint32_t Qh = sb, Ql = sb + QBYTES;
    const uint32_t KV = sb + 2 * QBYTES;

    const int tid = threadIdx.x, warp = tid >> 5, lane = tid & 31;
    const int g = lane >> 2, tq = lane & 3;
    const int qt = blockIdx.x, bh = blockIdx.y;
    const int b = bh >> 4, h = bh & 15;
    const int t0 = qt * 128;
    int nk = (qt == 0) ? 33 : (2 * qt + 2);
    if (nk > 33) nk = 33;

    const __nv_bfloat16* qsrc_h = qh_g + (size_t)b * TT * QKV_COLS + h * 64;
    const __nv_bfloat16* qsrc_l = ql_g + (size_t)b * TT * QKV_COLS + h * 64;
    const __nv_bfloat16* src_h[4] = { qsrc_h + CC, qsrc_l + CC,
                                      qsrc_h + 2*CC, qsrc_l + 2*CC };

#pragma unroll
    for (int i = 0; i < 4; ++i) {
        int u = tid + (i << 8);
        int r = u >> 3, dg = u & 7;
        int t = t0 + r; if (t >= TT) t = TT - 1;
        cp16(Qh + r * 144 + dg * 16, qsrc_h + (size_t)t * QKV_COLS + dg * 8);
    }
#pragma unroll
    for (int i = 0; i < 4; ++i) {
        int u = tid + (i << 8);
        int r = u >> 3, dg = u & 7;
        int t = t0 + r; if (t >= TT) t = TT - 1;
        cp16(Ql + r * 144 + dg * 16, qsrc_l + (size_t)t * QKV_COLS + dg * 8);
    }
    cp_commit();

    auto load_kv = [&](int buf, int s0) {
        uint32_t base = KV + buf * STAGEB;
#pragma unroll
        for (int a = 0; a < 4; ++a) {
#pragma unroll
            for (int i = 0; i < 2; ++i) {
                int u = tid + (i << 8);
                int r = u >> 3, dg = u & 7;
                int s = s0 + r; if (s >= TT) s = TT - 1;
                cp16(base + a * TBYTES + r * 144 + dg * 16,
                     src_h[a] + (size_t)s * QKV_COLS + dg * 8);
            }
        }
    };

    load_kv(0, 0);
    cp_commit();
    load_kv(1, 64);
    cp_commit();
    cp_wait1();
    __syncthreads();

    const uint32_t qrowoff = (uint32_t)((warp * 16 + (lane & 7) + ((lane >> 3) & 1) * 8) * 144
                                        + ((lane >> 4) & 1) * 16);
    uint32_t qfh[4][4], qfl[4][4];
#pragma unroll
    for (int k = 0; k < 4; ++k) {
        ldm4(qfh[k][0], qfh[k][1], qfh[k][2], qfh[k][3], Qh + qrowoff + k * 32);
        ldm4(qfl[k][0], qfl[k][1], qfl[k][2], qfl[k][3], Ql + qrowoff + k * 32);
    }

    const uint32_t krowpart = (uint32_t)(((lane & 7) + ((lane >> 4) & 1) * 8) * 144
                                         + ((lane >> 3) & 1) * 16);
    const uint32_t vrowpart = (uint32_t)(((lane & 7) + ((lane >> 3) & 1) * 8) * 144
                                         + ((lane >> 4) & 1) * 16);

    const int rowA = t0 + warp * 16 + g;
    const int rowB = rowA + 8;
    const int warpRowMin = t0 + warp * 16;

    float mA = -INFINITY, mB = -INFINITY, lA = 0.f, lB = 0.f;
    float o[8][4];
#pragma unroll
    for (int d = 0; d < 8; ++d)
#pragma unroll
        for (int c = 0; c < 4; ++c) o[d][c] = 0.f;

    for (int kt = 0; kt < nk; ++kt) {
        const int buf = kt & 1;
        const int s0 = kt * 64;
        const uint32_t kvb = KV + buf * STAGEB;

        float s[8][4];
#pragma unroll
        for (int j = 0; j < 8; ++j)
#pragma unroll
            for (int c = 0; c < 4; ++c) s[j][c] = 0.f;

#pragma unroll
        for (int k = 0; k < 4; ++k) {
            uint32_t kh[8][2], kl[8][2];
#pragma unroll
            for (int j = 0; j < 4; ++j) {
                uint32_t a = kvb + (uint32_t)(16 * j * 144) + krowpart + k * 32;
                ldm4(kh[2*j][0], kh[2*j][1], kh[2*j+1][0], kh[2*j+1][1], a);
                ldm4(kl[2*j][0], kl[2*j][1], kl[2*j+1][0], kl[2*j+1][1], a + TBYTES);
            }
#pragma unroll
            for (int jn = 0; jn < 8; ++jn) {
                mma_bf16(s[jn], qfh[k], kh[jn][0], kh[jn][1]);
                mma_bf16(s[jn], qfh[k], kl[jn][0], kl[jn][1]);
                mma_bf16(s[jn], qfl[k], kh[jn][0], kh[jn][1]);
            }
        }

        const bool need_mask = (s0 + 63 > warpRowMin) || (s0 + 63 >= TT);
        if (need_mask) {
#pragma unroll
            for (int jn = 0; jn < 8; ++jn) {
                int sc = s0 + 8 * jn + 2 * tq;
#pragma unroll
                for (int c = 0; c < 4; ++c) {
                    int sidx = sc + (c & 1);
                    int t = (c < 2) ? rowA : rowB;
                    bool ok = (sidx < TT) && (sidx <= t || t == 0);
                    if (!ok) s[jn][c] = -1e30f;
                }
            }
        }

        float tmA = -1e30f, tmB = -1e30f;
#pragma unroll
        for (int jn = 0; jn < 8; ++jn) {
            tmA = fmaxf(tmA, fmaxf(s[jn][0], s[jn][1]));
            tmB = fmaxf(tmB, fmaxf(s[jn][2], s[jn][3]));
        }
        tmA = fmaxf(tmA, __shfl_xor_sync(0xffffffffu, tmA, 1));
        tmA = fmaxf(tmA, __shfl_xor_sync(0xffffffffu, tmA, 2));
        tmB = fmaxf(tmB, __shfl_xor_sync(0xffffffffu, tmB, 1));
        tmB = fmaxf(tmB, __shfl_xor_sync(0xffffffffu, tmB, 2));

        float mAn = fmaxf(mA, tmA), mBn = fmaxf(mB, tmB);
        float facA = __expf(mA - mAn), facB = __expf(mB - mBn);
        mA = mAn; mB = mBn;

        float sumA = 0.f, sumB = 0.f;
#pragma unroll
        for (int jn = 0; jn < 8; ++jn) {
            s[jn][0] = __expf(s[jn][0] - mAn);
            s[jn][1] = __expf(s[jn][1] - mAn);
            s[jn][2] = __expf(s[jn][2] - mBn);
            s[jn][3] = __expf(s[jn][3] - mBn);
            sumA += s[jn][0] + s[jn][1];
            sumB += s[jn][2] + s[jn][3];
        }
        sumA += __shfl_xor_sync(0xffffffffu, sumA, 1);
        sumA += __shfl_xor_sync(0xffffffffu, sumA, 2);
        sumB += __shfl_xor_sync(0xffffffffu, sumB, 1);
        sumB += __shfl_xor_sync(0xffffffffu, sumB, 2);

        lA = lA * facA + sumA;
        lB = lB * facB + sumB;
#pragma unroll
        for (int d = 0; d < 8; ++d) {
            o[d][0] *= facA; o[d][1] *= facA;
            o[d][2] *= facB; o[d][3] *= facB;
        }

        uint32_t ph[4][4], pl[4][4];
#pragma unroll
        for (int k = 0; k < 4; ++k) {
            pack_hilo(s[2*k][0],   s[2*k][1],   ph[k][0], pl[k][0]);
            pack_hilo(s[2*k][2],   s[2*k][3],   ph[k][1], pl[k][1]);
            pack_hilo(s[2*k+1][0], s[2*k+1][1], ph[k][2], pl[k][2]);
            pack_hilo(s[2*k+1][2], s[2*k+1][3], ph[k][3], pl[k][3]);
        }

#pragma unroll
        for (int k = 0; k < 4; ++k) {
            const uint32_t vbase = kvb + 2 * TBYTES + (uint32_t)(16 * k * 144) + vrowpart;
#pragma unroll
            for (int jd = 0; jd < 4; ++jd) {
                uint32_t vh0, vh1, vh2, vh3, vl0, vl1, vl2, vl3;
                ldm4t(vh0, vh1, vh2, vh3, vbase + jd * 32);
                ldm4t(vl0, vl1, vl2, vl3, vbase + jd * 32 + TBYTES);
                mma_bf16(o[2*jd],   ph[k], vh0, vh1);
                mma_bf16(o[2*jd],   ph[k], vl0, vl1);
                mma_bf16(o[2*jd],   pl[k], vh0, vh1);
                mma_bf16(o[2*jd+1], ph[k], vh2, vh3);
                mma_bf16(o[2*jd+1], ph[k], vl2, vl3);
                mma_bf16(o[2*jd+1], pl[k], vh2, vh3);
            }
        }

        __syncthreads();
        if (kt + 2 < nk) load_kv(buf, (kt + 2) * 64);
        cp_commit();
        cp_wait1();
        __syncthreads();
    }

    // epilogue — write y tf32-rounded (proj GEMM reads it raw)
    if (rowA < TT) {
        float il = 1.f / lA;
        float* dst = y + (size_t)(b * TT + rowA) * CC + h * 64 + tq * 2;
#pragma unroll
        for (int d = 0; d < 8; ++d)
            *(float2*)(dst + d * 8) =
                make_float2(rnd_tf32(o[d][0] * il), rnd_tf32(o[d][1] * il));
    }
    if (rowB < TT) {
        float il = 1.f / lB;
        float* dst = y + (size_t)(b * TT + rowB) * CC + h * 64 + tq * 2;
#pragma unroll
        for (int d = 0; d < 8; ++d)
            *(float2*)(dst + d * 8) =
                make_float2(rnd_tf32(o[d][2] * il), rnd_tf32(o[d][3] * il));
    }
}

// ---------------------------------------------------------------------------
extern "C" void kernel_launch(void* const* d_in, const int* in_sizes, int n_in,
                              void* d_out, int out_size)
{
    const float* x      = (const float*)d_in[0];
    const float* W_attn = (const float*)d_in[1];
    const float* W_proj = (const float*)d_in[2];
    float* out = (float*)d_out;

    float *xr = nullptr, *y = nullptr, *wt_attn = nullptr, *wt_proj = nullptr;
    __nv_bfloat16 *qkv_hi = nullptr, *qkv_lo = nullptr;
    cudaGetSymbolAddress((void**)&xr, g_xr);
    cudaGetSymbolAddress((void**)&y, g_y);
    cudaGetSymbolAddress((void**)&wt_attn, g_wt_attn);
    cudaGetSymbolAddress((void**)&wt_proj, g_wt_proj);
    cudaGetSymbolAddress((void**)&qkv_hi, g_qkv_hi);
    cudaGetSymbolAddress((void**)&qkv_lo, g_qkv_lo);

    cudaFuncSetAttribute(tc_gemm2_kernel<0>,
                         cudaFuncAttributeMaxDynamicSharedMemorySize, GSMEM);
    cudaFuncSetAttribute(tc_gemm2_kernel<1>,
                         cudaFuncAttributeMaxDynamicSharedMemorySize, GSMEM);

    // 0) round x; transpose+round weights
    {
        size_t n4 = (size_t)MROWS * CC / 4;
        round_kernel<<<(int)((n4 + 255) / 256), 256>>>(x, xr, n4);
        dim3 blk(32, 8);
        transpose_kernel<<<dim3(QKV_COLS / 32, CC / 32), blk>>>(W_attn, wt_attn, CC, QKV_COLS);
        transpose_kernel<<<dim3(CC / 32, CC / 32), blk>>>(W_proj, wt_proj, CC, CC);
    }

    // 1) qkv = xr @ W_attn, epilogue splits to bf16 hi/lo with Q scale
    {
        dim3 grid(QKV_COLS / 128, (MROWS + 127) / 128);
        tc_gemm2_kernel<1><<<grid, 256, GSMEM>>>(
            xr, wt_attn, nullptr, qkv_hi, qkv_lo, MROWS, QKV_COLS, CC);
    }

    // 2) attention -> y (tf32-rounded fp32)
    {
        cudaFuncSetAttribute(attn_tc_kernel,
                             cudaFuncAttributeMaxDynamicSharedMemorySize, ATT_SMEM);
        dim3 grid(17, BB * HH);
        attn_tc_kernel<<<grid, 256, ATT_SMEM>>>(qkv_hi, qkv_lo, y);
    }

    // 3) out = y @ W_proj
    {
        dim3 grid(CC / 128, (MROWS + 127) / 128);
        tc_gemm2_kernel<0><<<grid, 256, GSMEM>>>(
            y, wt_proj, out, nullptr, nullptr, MROWS, CC, CC);
    }
}

// round 7
// speedup vs baseline: 3.5821x; 1.0511x over previous
#include <cuda_runtime.h>
#include <cuda_bf16.h>
#include <math.h>
#include <stdint.h>

// Problem constants
#define BB 4
#define TT 2049
#define CC 1024
#define HH 16
#define DD 64
#define MROWS (BB*TT)          // 8196
#define QKV_COLS (3*CC)        // 3072

// Scratch (device globals: allocation-free, graph-capturable)
__device__ float g_xr[(size_t)MROWS * CC];          // x, tf32-rounded
__device__ float g_y[(size_t)MROWS * CC];           // attention out (tf32-rounded)
__device__ float g_wt_attn[(size_t)QKV_COLS * CC];  // W_attn^T (tf32-rounded)
__device__ float g_wt_proj[(size_t)CC * CC];        // W_proj^T (tf32-rounded)
__device__ float g_qf[(size_t)MROWS * CC];          // Q (tf32-rounded, /8)
__device__ float g_kf[(size_t)MROWS * CC];          // K (tf32-rounded)
__device__ __nv_bfloat16 g_vh[(size_t)MROWS * CC];  // V hi
__device__ __nv_bfloat16 g_vl[(size_t)MROWS * CC];  // V lo

// ---------------------------------------------------------------------------
// helpers
// ---------------------------------------------------------------------------
__device__ __forceinline__ uint32_t smem_u32(const void* p) {
    uint32_t a;
    asm("{ .reg .u64 t; cvta.to.shared.u64 t, %1; cvt.u32.u64 %0, t; }" : "=r"(a) : "l"(p));
    return a;
}
__device__ __forceinline__ void cp16(uint32_t s, const void* g) {
    asm volatile("cp.async.cg.shared.global [%0], [%1], 16;" :: "r"(s), "l"(g));
}
__device__ __forceinline__ void cp_commit() {
    asm volatile("cp.async.commit_group;" ::: "memory");
}
__device__ __forceinline__ void cp_wait1() {
    asm volatile("cp.async.wait_group 1;" ::: "memory");
}
__device__ __forceinline__ uint32_t f2tf32(float f) {
    uint32_t u;
    asm("cvt.rna.tf32.f32 %0, %1;" : "=r"(u) : "f"(f));
    return u;
}
__device__ __forceinline__ float rnd_tf32(float f) {
    return __uint_as_float(f2tf32(f));
}
__device__ __forceinline__ void mma_tf32(float* d, const uint32_t* a, uint32_t b0, uint32_t b1) {
    asm volatile(
        "mma.sync.aligned.m16n8k8.row.col.f32.tf32.tf32.f32 "
        "{%0,%1,%2,%3}, {%4,%5,%6,%7}, {%8,%9}, {%0,%1,%2,%3};"
        : "+f"(d[0]), "+f"(d[1]), "+f"(d[2]), "+f"(d[3])
        : "r"(a[0]), "r"(a[1]), "r"(a[2]), "r"(a[3]), "r"(b0), "r"(b1));
}
__device__ __forceinline__ void mma_bf16(float* d, const uint32_t* a, uint32_t b0, uint32_t b1) {
    asm volatile(
        "mma.sync.aligned.m16n8k16.row.col.f32.bf16.bf16.f32 "
        "{%0,%1,%2,%3}, {%4,%5,%6,%7}, {%8,%9}, {%0,%1,%2,%3};"
        : "+f"(d[0]), "+f"(d[1]), "+f"(d[2]), "+f"(d[3])
        : "r"(a[0]), "r"(a[1]), "r"(a[2]), "r"(a[3]), "r"(b0), "r"(b1));
}
__device__ __forceinline__ void ldm4(uint32_t& r0, uint32_t& r1, uint32_t& r2, uint32_t& r3,
                                     uint32_t a) {
    asm volatile("ldmatrix.sync.aligned.m8n8.x4.shared.b16 {%0,%1,%2,%3}, [%4];"
                 : "=r"(r0), "=r"(r1), "=r"(r2), "=r"(r3) : "r"(a));
}
__device__ __forceinline__ void ldm4t(uint32_t& r0, uint32_t& r1, uint32_t& r2, uint32_t& r3,
                                      uint32_t a) {
    asm volatile("ldmatrix.sync.aligned.m8n8.x4.trans.shared.b16 {%0,%1,%2,%3}, [%4];"
                 : "=r"(r0), "=r"(r1), "=r"(r2), "=r"(r3) : "r"(a));
}
// split two fp32 into packed bf16 hi + lo (low half = p0)
__device__ __forceinline__ void pack_hilo(float p0, float p1, uint32_t& hi, uint32_t& lo) {
    uint32_t hh;
    asm("cvt.rn.bf16x2.f32 %0, %1, %2;" : "=r"(hh) : "f"(p1), "f"(p0));
    float h0 = __uint_as_float(hh << 16);
    float h1 = __uint_as_float(hh & 0xffff0000u);
    float l0 = p0 - h0, l1 = p1 - h1;
    uint32_t ll;
    asm("cvt.rn.bf16x2.f32 %0, %1, %2;" : "=r"(ll) : "f"(l1), "f"(l0));
    hi = hh; lo = ll;
}

// ---------------------------------------------------------------------------
// Transpose + tf32 round: out[c][r] = rnd(in[r][c])
// ---------------------------------------------------------------------------
__global__ __launch_bounds__(256) void transpose_kernel(
    const float* __restrict__ in, float* __restrict__ out, int R, int Ccols)
{
    __shared__ float t[32][33];
    int x = blockIdx.x * 32 + threadIdx.x;
    int y0 = blockIdx.y * 32;
#pragma unroll
    for (int j = threadIdx.y; j < 32; j += 8)
        t[j][threadIdx.x] = in[(size_t)(y0 + j) * Ccols + x];
    __syncthreads();
    int ox = y0 + threadIdx.x;
    int oy0 = blockIdx.x * 32;
#pragma unroll
    for (int j = threadIdx.y; j < 32; j += 8)
        out[(size_t)(oy0 + j) * R + ox] = rnd_tf32(t[threadIdx.x][j]);
}

// ---------------------------------------------------------------------------
// Elementwise tf32 round (float4)
// ---------------------------------------------------------------------------
__global__ __launch_bounds__(256) void round_kernel(
    const float* __restrict__ in, float* __restrict__ out, size_t n4)
{
    size_t i = (size_t)blockIdx.x * 256 + threadIdx.x;
    if (i < n4) {
        float4 v = ((const float4*)in)[i];
        v.x = rnd_tf32(v.x); v.y = rnd_tf32(v.y);
        v.z = rnd_tf32(v.z); v.w = rnd_tf32(v.w);
        ((float4*)out)[i] = v;
    }
}

// ---------------------------------------------------------------------------
// TF32 tensor-core GEMM, 3-stage single-sync pipeline.
// C(MxN) = A(MxK) @ Bt(NxK)^T. 128x128 tile, BK=32, 256 thr (2Mx4N warps).
// MODE 0: fp32 C. MODE 1: QKV epilogue (Q fp32/8, K fp32, V bf16 hi/lo).
// ---------------------------------------------------------------------------
#define GTILEB 18432                 // 128 x 36 floats
#define GSTAGE (2 * GTILEB)          // A + B
#define GSMEM (3 * GSTAGE)           // 110592

template<int MODE>
__global__ __launch_bounds__(256, 2) void tc_gemm2_kernel(
    const float* __restrict__ A, const float* __restrict__ Bt,
    float* __restrict__ Cf, float* __restrict__ Qf, float* __restrict__ Kf,
    __nv_bfloat16* __restrict__ Vh, __nv_bfloat16* __restrict__ Vl,
    int M, int N, int K)
{
    extern __shared__ float gsm[];
    const uint32_t sb = smem_u32(gsm);
    const uint32_t aBase[3] = { sb, sb + GSTAGE, sb + 2 * GSTAGE };
    const uint32_t bBase[3] = { sb + GTILEB, sb + GSTAGE + GTILEB, sb + 2 * GSTAGE + GTILEB };

    const int tid  = threadIdx.x;
    const int warp = tid >> 5;
    const int lane = tid & 31;
    const int wm = warp >> 2;
    const int wn = warp & 3;
    const int g  = lane >> 2;
    const int tq = lane & 3;

    const int bm = blockIdx.y * 128;
    const int bn = blockIdx.x * 128;
    const int NT = K >> 5;

    auto load_stage = [&](int s, int k0) {
#pragma unroll
        for (int i = 0; i < 4; ++i) {
            int u = tid + (i << 8);
            int r = u >> 3, c = u & 7;
            int ar = bm + r; if (ar >= M) ar = M - 1;
            cp16(aBase[s] + (uint32_t)(r * 144 + c * 16),
                 A + (size_t)ar * K + k0 + c * 4);
        }
#pragma unroll
        for (int i = 0; i < 4; ++i) {
            int u = tid + (i << 8);
            int r = u >> 3, c = u & 7;
            int br = bn + r; if (br >= N) br = N - 1;
            cp16(bBase[s] + (uint32_t)(r * 144 + c * 16),
                 Bt + (size_t)br * K + k0 + c * 4);
        }
    };

    const int sub = lane >> 3, srow = lane & 7;
    const uint32_t aOff = (uint32_t)(((sub & 1) * 8 + srow) * 144 + (sub >> 1) * 16);
    const uint32_t bOff = (uint32_t)(((sub >> 1) * 8 + srow) * 144 + (sub & 1) * 16);

    float acc[4][4][4];
#pragma unroll
    for (int i = 0; i < 4; ++i)
#pragma unroll
        for (int j = 0; j < 4; ++j)
#pragma unroll
            for (int r = 0; r < 4; ++r) acc[i][j][r] = 0.f;

    // prologue
    load_stage(0, 0);
    cp_commit();
    load_stage(1, 32);
    cp_commit();
    cp_wait1();
    __syncthreads();

    int slot = 0;
    for (int kt = 0; kt < NT; ++kt) {
        const int nst = kt + 2;
        if (nst < NT) load_stage(nst % 3, nst << 5);
        cp_commit();

        const uint32_t aW = aBase[slot] + (uint32_t)(wm * 64 * 144) + aOff;
        const uint32_t bW = bBase[slot] + (uint32_t)(wn * 32 * 144) + bOff;

#pragma unroll
        for (int ks = 0; ks < 4; ++ks) {
            uint32_t af[4][4], bf[2][4];
#pragma unroll
            for (int im = 0; im < 4; ++im)
                ldm4(af[im][0], af[im][1], af[im][2], af[im][3],
                     aW + (uint32_t)(im * 16 * 144) + ks * 32);
#pragma unroll
            for (int jp = 0; jp < 2; ++jp)
                ldm4(bf[jp][0], bf[jp][1], bf[jp][2], bf[jp][3],
                     bW + (uint32_t)(jp * 16 * 144) + ks * 32);
#pragma unroll
            for (int im = 0; im < 4; ++im)
#pragma unroll
                for (int jn = 0; jn < 4; ++jn)
                    mma_tf32(acc[im][jn], af[im], bf[jn >> 1][(jn & 1) * 2],
                             bf[jn >> 1][(jn & 1) * 2 + 1]);
        }

        cp_wait1();
        __syncthreads();
        slot = (slot == 2) ? 0 : slot + 1;
    }

    // epilogue
#pragma unroll
    for (int im = 0; im < 4; ++im) {
        const int r0 = bm + wm * 64 + im * 16 + g;
#pragma unroll
        for (int jn = 0; jn < 4; ++jn) {
            const int cc = bn + wn * 32 + jn * 8 + tq * 2;
            if (MODE == 0) {
                if (r0 < M)
                    *(float2*)&Cf[(size_t)r0 * N + cc] =
                        make_float2(acc[im][jn][0], acc[im][jn][1]);
                if (r0 + 8 < M)
                    *(float2*)&Cf[(size_t)(r0 + 8) * N + cc] =
                        make_float2(acc[im][jn][2], acc[im][jn][3]);
            } else {
                if (cc < CC) {            // Q: fp32, x0.125, tf32-rounded
                    if (r0 < M)
                        *(float2*)&Qf[(size_t)r0 * CC + cc] =
                            make_float2(rnd_tf32(acc[im][jn][0] * 0.125f),
                                        rnd_tf32(acc[im][jn][1] * 0.125f));
                    if (r0 + 8 < M)
                        *(float2*)&Qf[(size_t)(r0 + 8) * CC + cc] =
                            make_float2(rnd_tf32(acc[im][jn][2] * 0.125f),
                                        rnd_tf32(acc[im][jn][3] * 0.125f));
                } else if (cc < 2 * CC) { // K: fp32, tf32-rounded
                    int kc = cc - CC;
                    if (r0 < M)
                        *(float2*)&Kf[(size_t)r0 * CC + kc] =
                            make_float2(rnd_tf32(acc[im][jn][0]),
                                        rnd_tf32(acc[im][jn][1]));
                    if (r0 + 8 < M)
                        *(float2*)&Kf[(size_t)(r0 + 8) * CC + kc] =
                            make_float2(rnd_tf32(acc[im][jn][2]),
                                        rnd_tf32(acc[im][jn][3]));
                } else {                  // V: bf16 hi/lo split
                    int vc = cc - 2 * CC;
                    if (r0 < M) {
                        uint32_t h, l;
                        pack_hilo(acc[im][jn][0], acc[im][jn][1], h, l);
                        size_t o = ((size_t)r0 * CC + vc) >> 1;
                        ((uint32_t*)Vh)[o] = h;
                        ((uint32_t*)Vl)[o] = l;
                    }
                    if (r0 + 8 < M) {
                        uint32_t h, l;
                        pack_hilo(acc[im][jn][2], acc[im][jn][3], h, l);
                        size_t o = ((size_t)(r0 + 8) * CC + vc) >> 1;
                        ((uint32_t*)Vh)[o] = h;
                        ((uint32_t*)Vl)[o] = l;
                    }
                }
            }
        }
    }
}

// ---------------------------------------------------------------------------
// Flash attention: S = QK^T via tf32 mma (fp32 operands in smem),
// PV via bf16x3 split. 128 q-rows x (b,h) per CTA, 8 warps (m16 each).
// KV: 3-stage single-sync cp.async pipeline, key tiles of 64.
// Stage layout: [K0 9216][K1 9216][Vh 9216][Vl 9216]; all tiles 64rows x 144B.
// ---------------------------------------------------------------------------
#define KTB 9216
#define QTB 18432                    // 128 x 36 floats
#define ASTAGE (4 * KTB)             // 36864
#define ATT_SMEM (2 * QTB + 3 * ASTAGE)   // 147456

__global__ __launch_bounds__(256) void attn_tc_kernel(
    const float* __restrict__ qf, const float* __restrict__ kf,
    const __nv_bfloat16* __restrict__ vh_g, const __nv_bfloat16* __restrict__ vl_g,
    float* __restrict__ y)
{
    extern __shared__ char asmem[];
    const uint32_t sb = smem_u32(asmem);
    const uint32_t Qb = sb;
    const uint32_t KV = sb + 2 * QTB;

    const int tid = threadIdx.x, warp = tid >> 5, lane = tid & 31;
    const int g = lane >> 2, tq = lane & 3;
    const int qt = blockIdx.x, bh = blockIdx.y;
    const int b = bh >> 4, h = bh & 15;
    const int t0 = qt * 128;
    int nk = (qt == 0) ? 33 : (2 * qt + 2);
    if (nk > 33) nk = 33;

    const float* qsrc = qf + (size_t)b * TT * CC + h * 64;
    const float* ksrc = kf + (size_t)b * TT * CC + h * 64;
    const __nv_bfloat16* vhsrc = vh_g + (size_t)b * TT * CC + h * 64;
    const __nv_bfloat16* vlsrc = vl_g + (size_t)b * TT * CC + h * 64;

    // Q loader: 2 subtiles of [128 rows][32 floats, 144B pitch]
    auto load_q = [&]() {
#pragma unroll
        for (int st = 0; st < 2; ++st)
#pragma unroll
            for (int i = 0; i < 4; ++i) {
                int u = tid + (i << 8);
                int r = u >> 3, c = u & 7;
                int t = t0 + r; if (t >= TT) t = TT - 1;
                cp16(Qb + st * QTB + r * 144 + c * 16,
                     qsrc + (size_t)t * CC + st * 32 + c * 4);
            }
    };

    // KV stage loader
    auto load_kv = [&](int slot, int s0) {
        uint32_t base = KV + slot * ASTAGE;
#pragma unroll
        for (int st = 0; st < 2; ++st)
#pragma unroll
            for (int i = 0; i < 2; ++i) {
                int u = tid + (i << 8);
                int r = u >> 3, c = u & 7;
                int s = s0 + r; if (s >= TT) s = TT - 1;
                cp16(base + st * KTB + r * 144 + c * 16,
                     ksrc + (size_t)s * CC + st * 32 + c * 4);
            }
#pragma unroll
        for (int i = 0; i < 2; ++i) {
            int u = tid + (i << 8);
            int r = u >> 3, c = u & 7;
            int s = s0 + r; if (s >= TT) s = TT - 1;
            cp16(base + 2 * KTB + r * 144 + c * 16, vhsrc + (size_t)s * CC + c * 8);
        }
#pragma unroll
        for (int i = 0; i < 2; ++i) {
            int u = tid + (i << 8);
            int r = u >> 3, c = u & 7;
            int s = s0 + r; if (s >= TT) s = TT - 1;
            cp16(base + 3 * KTB + r * 144 + c * 16, vlsrc + (size_t)s * CC + c * 8);
        }
    };

    // prologue: Q + stage 0 | stage 1
    load_q();
    load_kv(0, 0);
    cp_commit();
    load_kv(1, 64);
    cp_commit();
    cp_wait1();
    __syncthreads();

    // fragment offset patterns (tf32 via b16-view ldmatrix)
    const int sub = lane >> 3, srow = lane & 7;
    const uint32_t aOff = (uint32_t)(((sub & 1) * 8 + srow) * 144 + (sub >> 1) * 16);
    const uint32_t bOff = (uint32_t)(((sub >> 1) * 8 + srow) * 144 + (sub & 1) * 16);
    const uint32_t vrowpart = (uint32_t)(((lane & 7) + ((lane >> 3) & 1) * 8) * 144
                                         + ((lane >> 4) & 1) * 16);

    // Q a-frags (persist): 8 k8-steps
    uint32_t aq[8][4];
#pragma unroll
    for (int ks = 0; ks < 8; ++ks)
        ldm4(aq[ks][0], aq[ks][1], aq[ks][2], aq[ks][3],
             Qb + (ks >> 2) * QTB + (uint32_t)(warp * 16 * 144) + aOff + (ks & 3) * 32);

    const int rowA = t0 + warp * 16 + g;
    const int rowB = rowA + 8;
    const int warpRowMin = t0 + warp * 16;

    float mA = -INFINITY, mB = -INFINITY, lA = 0.f, lB = 0.f;
    float o[8][4];
#pragma unroll
    for (int d = 0; d < 8; ++d)
#pragma unroll
        for (int c = 0; c < 4; ++c) o[d][c] = 0.f;

    int slot = 0;
    for (int kt = 0; kt < nk; ++kt) {
        const int s0 = kt * 64;
        const int nst = kt + 2;
        if (nst < nk) load_kv(nst % 3, nst * 64);
        cp_commit();

        const uint32_t kvb = KV + slot * ASTAGE;

        // ---- S = Q K^T (tf32) ----
        float s[8][4];
#pragma unroll
        for (int j = 0; j < 8; ++j)
#pragma unroll
            for (int c = 0; c < 4; ++c) s[j][c] = 0.f;

#pragma unroll
        for (int ks = 0; ks < 8; ++ks) {
            const uint32_t kb = kvb + (ks >> 2) * KTB + (ks & 3) * 32 + bOff;
            uint32_t bfr[4][4];
#pragma unroll
            for (int jp = 0; jp < 4; ++jp)
                ldm4(bfr[jp][0], bfr[jp][1], bfr[jp][2], bfr[jp][3],
                     kb + (uint32_t)(jp * 16 * 144));
#pragma unroll
            for (int jn = 0; jn < 8; ++jn)
                mma_tf32(s[jn], aq[ks], bfr[jn >> 1][(jn & 1) * 2],
                         bfr[jn >> 1][(jn & 1) * 2 + 1]);
        }

        // ---- mask ----
        const bool need_mask = (s0 + 63 > warpRowMin) || (s0 + 63 >= TT);
        if (need_mask) {
#pragma unroll
            for (int jn = 0; jn < 8; ++jn) {
                int sc = s0 + 8 * jn + 2 * tq;
#pragma unroll
                for (int c = 0; c < 4; ++c) {
                    int sidx = sc + (c & 1);
                    int t = (c < 2) ? rowA : rowB;
                    bool ok = (sidx < TT) && (sidx <= t || t == 0);
                    if (!ok) s[jn][c] = -1e30f;
                }
            }
        }

        // ---- online softmax ----
        float tmA = -1e30f, tmB = -1e30f;
#pragma unroll
        for (int jn = 0; jn < 8; ++jn) {
            tmA = fmaxf(tmA, fmaxf(s[jn][0], s[jn][1]));
            tmB = fmaxf(tmB, fmaxf(s[jn][2], s[jn][3]));
        }
        tmA = fmaxf(tmA, __shfl_xor_sync(0xffffffffu, tmA, 1));
        tmA = fmaxf(tmA, __shfl_xor_sync(0xffffffffu, tmA, 2));
        tmB = fmaxf(tmB, __shfl_xor_sync(0xffffffffu, tmB, 1));
        tmB = fmaxf(tmB, __shfl_xor_sync(0xffffffffu, tmB, 2));

        float mAn = fmaxf(mA, tmA), mBn = fmaxf(mB, tmB);
        float facA = __expf(mA - mAn), facB = __expf(mB - mBn);
        mA = mAn; mB = mBn;

        float sumA = 0.f, sumB = 0.f;
#pragma unroll
        for (int jn = 0; jn < 8; ++jn) {
            s[jn][0] = __expf(s[jn][0] - mAn);
            s[jn][1] = __expf(s[jn][1] - mAn);
            s[jn][2] = __expf(s[jn][2] - mBn);
            s[jn][3] = __expf(s[jn][3] - mBn);
            sumA += s[jn][0] + s[jn][1];
            sumB += s[jn][2] + s[jn][3];
        }
        sumA += __shfl_xor_sync(0xffffffffu, sumA, 1);
        sumA += __shfl_xor_sync(0xffffffffu, sumA, 2);
        sumB += __shfl_xor_sync(0xffffffffu, sumB, 1);
        sumB += __shfl_xor_sync(0xffffffffu, sumB, 2);

        lA = lA * facA + sumA;
        lB = lB * facB + sumB;
#pragma unroll
        for (int d = 0; d < 8; ++d) {
            o[d][0] *= facA; o[d][1] *= facA;
            o[d][2] *= facB; o[d][3] *= facB;
        }

        // ---- pack P to bf16 hi/lo (A-fragments for PV) ----
        uint32_t ph[4][4], pl[4][4];
#pragma unroll
        for (int k = 0; k < 4; ++k) {
            pack_hilo(s[2*k][0],   s[2*k][1],   ph[k][0], pl[k][0]);
            pack_hilo(s[2*k][2],   s[2*k][3],   ph[k][1], pl[k][1]);
            pack_hilo(s[2*k+1][0], s[2*k+1][1], ph[k][2], pl[k][2]);
            pack_hilo(s[2*k+1][2], s[2*k+1][3], ph[k][3], pl[k][3]);
        }

        // ---- O += P V (bf16x3) ----
#pragma unroll
        for (int k = 0; k < 4; ++k) {
            const uint32_t vbase = kvb + 2 * KTB + (uint32_t)(16 * k * 144) + vrowpart;
#pragma unroll
            for (int jd = 0; jd < 4; ++jd) {
                uint32_t vh0, vh1, vh2, vh3, vl0, vl1, vl2, vl3;
                ldm4t(vh0, vh1, vh2, vh3, vbase + jd * 32);
                ldm4t(vl0, vl1, vl2, vl3, vbase + jd * 32 + KTB);
                mma_bf16(o[2*jd],   ph[k], vh0, vh1);
                mma_bf16(o[2*jd],   ph[k], vl0, vl1);
                mma_bf16(o[2*jd],   pl[k], vh0, vh1);
                mma_bf16(o[2*jd+1], ph[k], vh2, vh3);
                mma_bf16(o[2*jd+1], ph[k], vl2, vl3);
                mma_bf16(o[2*jd+1], pl[k], vh2, vh3);
            }
        }

        cp_wait1();
        __syncthreads();
        slot = (slot == 2) ? 0 : slot + 1;
    }

    // epilogue — write y tf32-rounded (proj GEMM reads it raw)
    if (rowA < TT) {
        float il = 1.f / lA;
        float* dst = y + (size_t)(b * TT + rowA) * CC + h * 64 + tq * 2;
#pragma unroll
        for (int d = 0; d < 8; ++d)
            *(float2*)(dst + d * 8) =
                make_float2(rnd_tf32(o[d][0] * il), rnd_tf32(o[d][1] * il));
    }
    if (rowB < TT) {
        float il = 1.f / lB;
        float* dst = y + (size_t)(b * TT + rowB) * CC + h * 64 + tq * 2;
#pragma unroll
        for (int d = 0; d < 8; ++d)
            *(float2*)(dst + d * 8) =
                make_float2(rnd_tf32(o[d][2] * il), rnd_tf32(o[d][3] * il));
    }
}

// ---------------------------------------------------------------------------
extern "C" void kernel_launch(void* const* d_in, const int* in_sizes, int n_in,
                              void* d_out, int out_size)
{
    const float* x      = (const float*)d_in[0];
    const float* W_attn = (const float*)d_in[1];
    const float* W_proj = (const float*)d_in[2];
    float* out = (float*)d_out;

    float *xr = nullptr, *y = nullptr, *wt_attn = nullptr, *wt_proj = nullptr;
    float *qf = nullptr, *kf = nullptr;
    __nv_bfloat16 *vh = nullptr, *vl = nullptr;
    cudaGetSymbolAddress((void**)&xr, g_xr);
    cudaGetSymbolAddress((void**)&y, g_y);
    cudaGetSymbolAddress((void**)&wt_attn, g_wt_attn);
    cudaGetSymbolAddress((void**)&wt_proj, g_wt_proj);
    cudaGetSymbolAddress((void**)&qf, g_qf);
    cudaGetSymbolAddress((void**)&kf, g_kf);
    cudaGetSymbolAddress((void**)&vh, g_vh);
    cudaGetSymbolAddress((void**)&vl, g_vl);

    cudaFuncSetAttribute(tc_gemm2_kernel<0>,
                         cudaFuncAttributeMaxDynamicSharedMemorySize, GSMEM);
    cudaFuncSetAttribute(tc_gemm2_kernel<1>,
                         cudaFuncAttributeMaxDynamicSharedMemorySize, GSMEM);
    cudaFuncSetAttribute(attn_tc_kernel,
                         cudaFuncAttributeMaxDynamicSharedMemorySize, ATT_SMEM);

    // 0) round x; transpose+round weights
    {
        size_t n4 = (size_t)MROWS * CC / 4;
        round_kernel<<<(int)((n4 + 255) / 256), 256>>>(x, xr, n4);
        dim3 blk(32, 8);
        transpose_kernel<<<dim3(QKV_COLS / 32, CC / 32), blk>>>(W_attn, wt_attn, CC, QKV_COLS);
        transpose_kernel<<<dim3(CC / 32, CC / 32), blk>>>(W_proj, wt_proj, CC, CC);
    }

    // 1) qkv GEMM: epilogue writes Q (fp32/8), K (fp32), V (bf16 hi/lo)
    {
        dim3 grid(QKV_COLS / 128, (MROWS + 127) / 128);
        tc_gemm2_kernel<1><<<grid, 256, GSMEM>>>(
            xr, wt_attn, nullptr, qf, kf, vh, vl, MROWS, QKV_COLS, CC);
    }

    // 2) attention -> y
    {
        dim3 grid(17, BB * HH);
        attn_tc_kernel<<<grid, 256, ATT_SMEM>>>(qf, kf, vh, vl, y);
    }

    // 3) out = y @ W_proj
    {
        dim3 grid(CC / 128, (MROWS + 127) / 128);
        tc_gemm2_kernel<0><<<grid, 256, GSMEM>>>(
            y, wt_proj, out, nullptr, nullptr, nullptr, nullptr, MROWS, CC, CC);
    }
}

// round 8
// speedup vs baseline: 3.6146x; 1.0091x over previous
#include <cuda_runtime.h>
#include <cuda_bf16.h>
#include <math.h>
#include <stdint.h>

// Problem constants
#define BB 4
#define TT 2049
#define CC 1024
#define HH 16
#define DD 64
#define MROWS (BB*TT)          // 8196
#define QKV_COLS (3*CC)        // 3072

// Scratch (device globals: allocation-free, graph-capturable)
__device__ float g_xr[(size_t)MROWS * CC];          // x, tf32-rounded
__device__ float g_y[(size_t)MROWS * CC];           // attention out (tf32-rounded)
__device__ float g_wt_attn[(size_t)QKV_COLS * CC];  // W_attn^T (tf32-rounded)
__device__ float g_wt_proj[(size_t)CC * CC];        // W_proj^T (tf32-rounded)
__device__ float g_qf[(size_t)MROWS * CC];          // Q (tf32-rounded, * log2e/8)
__device__ float g_kf[(size_t)MROWS * CC];          // K (tf32-rounded)
__device__ __nv_bfloat16 g_vh[(size_t)MROWS * CC];  // V hi
__device__ __nv_bfloat16 g_vl[(size_t)MROWS * CC];  // V lo

#define QSCALE 0.18033688011112042f   // 0.125 * log2(e)

// ---------------------------------------------------------------------------
// helpers
// ---------------------------------------------------------------------------
__device__ __forceinline__ uint32_t smem_u32(const void* p) {
    uint32_t a;
    asm("{ .reg .u64 t; cvta.to.shared.u64 t, %1; cvt.u32.u64 %0, t; }" : "=r"(a) : "l"(p));
    return a;
}
__device__ __forceinline__ void cp16(uint32_t s, const void* g) {
    asm volatile("cp.async.cg.shared.global [%0], [%1], 16;" :: "r"(s), "l"(g));
}
__device__ __forceinline__ void cp_commit() {
    asm volatile("cp.async.commit_group;" ::: "memory");
}
__device__ __forceinline__ void cp_wait1() {
    asm volatile("cp.async.wait_group 1;" ::: "memory");
}
__device__ __forceinline__ uint32_t f2tf32(float f) {
    uint32_t u;
    asm("cvt.rna.tf32.f32 %0, %1;" : "=r"(u) : "f"(f));
    return u;
}
__device__ __forceinline__ float rnd_tf32(float f) {
    return __uint_as_float(f2tf32(f));
}
__device__ __forceinline__ float ex2f(float f) {
    float r;
    asm("ex2.approx.f32 %0, %1;" : "=f"(r) : "f"(f));
    return r;
}
__device__ __forceinline__ void mma_tf32(float* d, const uint32_t* a, uint32_t b0, uint32_t b1) {
    asm volatile(
        "mma.sync.aligned.m16n8k8.row.col.f32.tf32.tf32.f32 "
        "{%0,%1,%2,%3}, {%4,%5,%6,%7}, {%8,%9}, {%0,%1,%2,%3};"
        : "+f"(d[0]), "+f"(d[1]), "+f"(d[2]), "+f"(d[3])
        : "r"(a[0]), "r"(a[1]), "r"(a[2]), "r"(a[3]), "r"(b0), "r"(b1));
}
__device__ __forceinline__ void mma_bf16(float* d, const uint32_t* a, uint32_t b0, uint32_t b1) {
    asm volatile(
        "mma.sync.aligned.m16n8k16.row.col.f32.bf16.bf16.f32 "
        "{%0,%1,%2,%3}, {%4,%5,%6,%7}, {%8,%9}, {%0,%1,%2,%3};"
        : "+f"(d[0]), "+f"(d[1]), "+f"(d[2]), "+f"(d[3])
        : "r"(a[0]), "r"(a[1]), "r"(a[2]), "r"(a[3]), "r"(b0), "r"(b1));
}
__device__ __forceinline__ void ldm4(uint32_t& r0, uint32_t& r1, uint32_t& r2, uint32_t& r3,
                                     uint32_t a) {
    asm volatile("ldmatrix.sync.aligned.m8n8.x4.shared.b16 {%0,%1,%2,%3}, [%4];"
                 : "=r"(r0), "=r"(r1), "=r"(r2), "=r"(r3) : "r"(a));
}
__device__ __forceinline__ void ldm4t(uint32_t& r0, uint32_t& r1, uint32_t& r2, uint32_t& r3,
                                      uint32_t a) {
    asm volatile("ldmatrix.sync.aligned.m8n8.x4.trans.shared.b16 {%0,%1,%2,%3}, [%4];"
                 : "=r"(r0), "=r"(r1), "=r"(r2), "=r"(r3) : "r"(a));
}
// split two fp32 into packed bf16 hi + lo (low half = p0)
__device__ __forceinline__ void pack_hilo(float p0, float p1, uint32_t& hi, uint32_t& lo) {
    uint32_t hh;
    asm("cvt.rn.bf16x2.f32 %0, %1, %2;" : "=r"(hh) : "f"(p1), "f"(p0));
    float h0 = __uint_as_float(hh << 16);
    float h1 = __uint_as_float(hh & 0xffff0000u);
    float l0 = p0 - h0, l1 = p1 - h1;
    uint32_t ll;
    asm("cvt.rn.bf16x2.f32 %0, %1, %2;" : "=r"(ll) : "f"(l1), "f"(l0));
    hi = hh; lo = ll;
}

// ---------------------------------------------------------------------------
// Transpose + tf32 round: out[c][r] = rnd(in[r][c])
// ---------------------------------------------------------------------------
__global__ __launch_bounds__(256) void transpose_kernel(
    const float* __restrict__ in, float* __restrict__ out, int R, int Ccols)
{
    __shared__ float t[32][33];
    int x = blockIdx.x * 32 + threadIdx.x;
    int y0 = blockIdx.y * 32;
#pragma unroll
    for (int j = threadIdx.y; j < 32; j += 8)
        t[j][threadIdx.x] = in[(size_t)(y0 + j) * Ccols + x];
    __syncthreads();
    int ox = y0 + threadIdx.x;
    int oy0 = blockIdx.x * 32;
#pragma unroll
    for (int j = threadIdx.y; j < 32; j += 8)
        out[(size_t)(oy0 + j) * R + ox] = rnd_tf32(t[threadIdx.x][j]);
}

// ---------------------------------------------------------------------------
// Elementwise tf32 round (float4)
// ---------------------------------------------------------------------------
__global__ __launch_bounds__(256) void round_kernel(
    const float* __restrict__ in, float* __restrict__ out, size_t n4)
{
    size_t i = (size_t)blockIdx.x * 256 + threadIdx.x;
    if (i < n4) {
        float4 v = ((const float4*)in)[i];
        v.x = rnd_tf32(v.x); v.y = rnd_tf32(v.y);
        v.z = rnd_tf32(v.z); v.w = rnd_tf32(v.w);
        ((float4*)out)[i] = v;
    }
}

// ---------------------------------------------------------------------------
// TF32 tensor-core GEMM, 3-stage single-sync pipeline.
// C(MxN) = A(MxK) @ Bt(NxK)^T. 128x128 tile, BK=32, 256 thr (2Mx4N warps).
// MODE 0: fp32 C. MODE 1: QKV epilogue (Q fp32*QSCALE, K fp32, V bf16 hi/lo).
// ---------------------------------------------------------------------------
#define GTILEB 18432                 // 128 x 36 floats
#define GSTAGE (2 * GTILEB)          // A + B
#define GSMEM (3 * GSTAGE)           // 110592

template<int MODE>
__global__ __launch_bounds__(256, 2) void tc_gemm2_kernel(
    const float* __restrict__ A, const float* __restrict__ Bt,
    float* __restrict__ Cf, float* __restrict__ Qf, float* __restrict__ Kf,
    __nv_bfloat16* __restrict__ Vh, __nv_bfloat16* __restrict__ Vl,
    int M, int N, int K)
{
    extern __shared__ float gsm[];
    const uint32_t sb = smem_u32(gsm);
    const uint32_t aBase[3] = { sb, sb + GSTAGE, sb + 2 * GSTAGE };
    const uint32_t bBase[3] = { sb + GTILEB, sb + GSTAGE + GTILEB, sb + 2 * GSTAGE + GTILEB };

    const int tid  = threadIdx.x;
    const int warp = tid >> 5;
    const int lane = tid & 31;
    const int wm = warp >> 2;
    const int wn = warp & 3;
    const int g  = lane >> 2;
    const int tq = lane & 3;

    const int bm = blockIdx.y * 128;
    const int bn = blockIdx.x * 128;
    const int NT = K >> 5;

    auto load_stage = [&](int s, int k0) {
#pragma unroll
        for (int i = 0; i < 4; ++i) {
            int u = tid + (i << 8);
            int r = u >> 3, c = u & 7;
            int ar = bm + r; if (ar >= M) ar = M - 1;
            cp16(aBase[s] + (uint32_t)(r * 144 + c * 16),
                 A + (size_t)ar * K + k0 + c * 4);
        }
#pragma unroll
        for (int i = 0; i < 4; ++i) {
            int u = tid + (i << 8);
            int r = u >> 3, c = u & 7;
            int br = bn + r; if (br >= N) br = N - 1;
            cp16(bBase[s] + (uint32_t)(r * 144 + c * 16),
                 Bt + (size_t)br * K + k0 + c * 4);
        }
    };

    const int sub = lane >> 3, srow = lane & 7;
    const uint32_t aOff = (uint32_t)(((sub & 1) * 8 + srow) * 144 + (sub >> 1) * 16);
    const uint32_t bOff = (uint32_t)(((sub >> 1) * 8 + srow) * 144 + (sub & 1) * 16);

    float acc[4][4][4];
#pragma unroll
    for (int i = 0; i < 4; ++i)
#pragma unroll
        for (int j = 0; j < 4; ++j)
#pragma unroll
            for (int r = 0; r < 4; ++r) acc[i][j][r] = 0.f;

    // prologue
    load_stage(0, 0);
    cp_commit();
    load_stage(1, 32);
    cp_commit();
    cp_wait1();
    __syncthreads();

    int slot = 0;
    for (int kt = 0; kt < NT; ++kt) {
        const int nst = kt + 2;
        if (nst < NT) load_stage(nst % 3, nst << 5);
        cp_commit();

        const uint32_t aW = aBase[slot] + (uint32_t)(wm * 64 * 144) + aOff;
        const uint32_t bW = bBase[slot] + (uint32_t)(wn * 32 * 144) + bOff;

#pragma unroll
        for (int ks = 0; ks < 4; ++ks) {
            uint32_t af[4][4], bf[2][4];
#pragma unroll
            for (int im = 0; im < 4; ++im)
                ldm4(af[im][0], af[im][1], af[im][2], af[im][3],
                     aW + (uint32_t)(im * 16 * 144) + ks * 32);
#pragma unroll
            for (int jp = 0; jp < 2; ++jp)
                ldm4(bf[jp][0], bf[jp][1], bf[jp][2], bf[jp][3],
                     bW + (uint32_t)(jp * 16 * 144) + ks * 32);
#pragma unroll
            for (int im = 0; im < 4; ++im)
#pragma unroll
                for (int jn = 0; jn < 4; ++jn)
                    mma_tf32(acc[im][jn], af[im], bf[jn >> 1][(jn & 1) * 2],
                             bf[jn >> 1][(jn & 1) * 2 + 1]);
        }

        cp_wait1();
        __syncthreads();
        slot = (slot == 2) ? 0 : slot + 1;
    }

    // epilogue
#pragma unroll
    for (int im = 0; im < 4; ++im) {
        const int r0 = bm + wm * 64 + im * 16 + g;
#pragma unroll
        for (int jn = 0; jn < 4; ++jn) {
            const int cc = bn + wn * 32 + jn * 8 + tq * 2;
            if (MODE == 0) {
                if (r0 < M)
                    *(float2*)&Cf[(size_t)r0 * N + cc] =
                        make_float2(acc[im][jn][0], acc[im][jn][1]);
                if (r0 + 8 < M)
                    *(float2*)&Cf[(size_t)(r0 + 8) * N + cc] =
                        make_float2(acc[im][jn][2], acc[im][jn][3]);
            } else {
                if (cc < CC) {            // Q: fp32, * log2e/8, tf32-rounded
                    if (r0 < M)
                        *(float2*)&Qf[(size_t)r0 * CC + cc] =
                            make_float2(rnd_tf32(acc[im][jn][0] * QSCALE),
                                        rnd_tf32(acc[im][jn][1] * QSCALE));
                    if (r0 + 8 < M)
                        *(float2*)&Qf[(size_t)(r0 + 8) * CC + cc] =
                            make_float2(rnd_tf32(acc[im][jn][2] * QSCALE),
                                        rnd_tf32(acc[im][jn][3] * QSCALE));
                } else if (cc < 2 * CC) { // K: fp32, tf32-rounded
                    int kc = cc - CC;
                    if (r0 < M)
                        *(float2*)&Kf[(size_t)r0 * CC + kc] =
                            make_float2(rnd_tf32(acc[im][jn][0]),
                                        rnd_tf32(acc[im][jn][1]));
                    if (r0 + 8 < M)
                        *(float2*)&Kf[(size_t)(r0 + 8) * CC + kc] =
                            make_float2(rnd_tf32(acc[im][jn][2]),
                                        rnd_tf32(acc[im][jn][3]));
                } else {                  // V: bf16 hi/lo split
                    int vc = cc - 2 * CC;
                    if (r0 < M) {
                        uint32_t h, l;
                        pack_hilo(acc[im][jn][0], acc[im][jn][1], h, l);
                        size_t o = ((size_t)r0 * CC + vc) >> 1;
                        ((uint32_t*)Vh)[o] = h;
                        ((uint32_t*)Vl)[o] = l;
                    }
                    if (r0 + 8 < M) {
                        uint32_t h, l;
                        pack_hilo(acc[im][jn][2], acc[im][jn][3], h, l);
                        size_t o = ((size_t)(r0 + 8) * CC + vc) >> 1;
                        ((uint32_t*)Vh)[o] = h;
                        ((uint32_t*)Vl)[o] = l;
                    }
                }
            }
        }
    }
}

// ---------------------------------------------------------------------------
// Flash attention: S = QK^T via tf32 mma, PV via bf16x3 split.
// log2-domain softmax (scale folded into Q). Fully-masked warps skip compute.
// 128 q-rows x (b,h) per CTA, 8 warps (m16 each), 64-key tiles,
// 3-stage single-sync cp.async pipeline.
// ---------------------------------------------------------------------------
#define KTB 9216
#define QTB 18432                    // 128 x 36 floats
#define ASTAGE (4 * KTB)             // 36864
#define ATT_SMEM (2 * QTB + 3 * ASTAGE)   // 147456

__global__ __launch_bounds__(256) void attn_tc_kernel(
    const float* __restrict__ qf, const float* __restrict__ kf,
    const __nv_bfloat16* __restrict__ vh_g, const __nv_bfloat16* __restrict__ vl_g,
    float* __restrict__ y)
{
    extern __shared__ char asmem[];
    const uint32_t sb = smem_u32(asmem);
    const uint32_t Qb = sb;
    const uint32_t KV = sb + 2 * QTB;

    const int tid = threadIdx.x, warp = tid >> 5, lane = tid & 31;
    const int g = lane >> 2, tq = lane & 3;
    const int qt = blockIdx.x, bh = blockIdx.y;
    const int b = bh >> 4, h = bh & 15;
    const int t0 = qt * 128;
    int nk = (qt == 0) ? 33 : (2 * qt + 2);
    if (nk > 33) nk = 33;

    const float* qsrc = qf + (size_t)b * TT * CC + h * 64;
    const float* ksrc = kf + (size_t)b * TT * CC + h * 64;
    const __nv_bfloat16* vhsrc = vh_g + (size_t)b * TT * CC + h * 64;
    const __nv_bfloat16* vlsrc = vl_g + (size_t)b * TT * CC + h * 64;

    auto load_q = [&]() {
#pragma unroll
        for (int st = 0; st < 2; ++st)
#pragma unroll
            for (int i = 0; i < 4; ++i) {
                int u = tid + (i << 8);
                int r = u >> 3, c = u & 7;
                int t = t0 + r; if (t >= TT) t = TT - 1;
                cp16(Qb + st * QTB + r * 144 + c * 16,
                     qsrc + (size_t)t * CC + st * 32 + c * 4);
            }
    };

    auto load_kv = [&](int slot, int s0) {
        uint32_t base = KV + slot * ASTAGE;
#pragma unroll
        for (int st = 0; st < 2; ++st)
#pragma unroll
            for (int i = 0; i < 2; ++i) {
                int u = tid + (i << 8);
                int r = u >> 3, c = u & 7;
                int s = s0 + r; if (s >= TT) s = TT - 1;
                cp16(base + st * KTB + r * 144 + c * 16,
                     ksrc + (size_t)s * CC + st * 32 + c * 4);
            }
#pragma unroll
        for (int i = 0; i < 2; ++i) {
            int u = tid + (i << 8);
            int r = u >> 3, c = u & 7;
            int s = s0 + r; if (s >= TT) s = TT - 1;
            cp16(base + 2 * KTB + r * 144 + c * 16, vhsrc + (size_t)s * CC + c * 8);
        }
#pragma unroll
        for (int i = 0; i < 2; ++i) {
            int u = tid + (i << 8);
            int r = u >> 3, c = u & 7;
            int s = s0 + r; if (s >= TT) s = TT - 1;
            cp16(base + 3 * KTB + r * 144 + c * 16, vlsrc + (size_t)s * CC + c * 8);
        }
    };

    load_q();
    load_kv(0, 0);
    cp_commit();
    load_kv(1, 64);
    cp_commit();
    cp_wait1();
    __syncthreads();

    const int sub = lane >> 3, srow = lane & 7;
    const uint32_t aOff = (uint32_t)(((sub & 1) * 8 + srow) * 144 + (sub >> 1) * 16);
    const uint32_t bOff = (uint32_t)(((sub >> 1) * 8 + srow) * 144 + (sub & 1) * 16);
    const uint32_t vrowpart = (uint32_t)(((lane & 7) + ((lane >> 3) & 1) * 8) * 144
                                         + ((lane >> 4) & 1) * 16);

    uint32_t aq[8][4];
#pragma unroll
    for (int ks = 0; ks < 8; ++ks)
        ldm4(aq[ks][0], aq[ks][1], aq[ks][2], aq[ks][3],
             Qb + (ks >> 2) * QTB + (uint32_t)(warp * 16 * 144) + aOff + (ks & 3) * 32);

    const int rowA = t0 + warp * 16 + g;
    const int rowB = rowA + 8;
    const int warpRowMin = t0 + warp * 16;
    const int warpRowMax = warpRowMin + 15;
    const bool hasRow0 = (warpRowMin == 0);    // state row attends everything

    float mA = -INFINITY, mB = -INFINITY, lA = 0.f, lB = 0.f;
    float o[8][4];
#pragma unroll
    for (int d = 0; d < 8; ++d)
#pragma unroll
        for (int c = 0; c < 4; ++c) o[d][c] = 0.f;

    int slot = 0;
    for (int kt = 0; kt < nk; ++kt) {
        const int s0 = kt * 64;
        const int nst = kt + 2;
        if (nst < nk) load_kv(nst % 3, nst * 64);
        cp_commit();

        const uint32_t kvb = KV + slot * ASTAGE;
        const bool active = (s0 <= warpRowMax) || hasRow0;

        if (active) {
            // ---- S = Q K^T (tf32) ----
            float s[8][4];
#pragma unroll
            for (int j = 0; j < 8; ++j)
#pragma unroll
                for (int c = 0; c < 4; ++c) s[j][c] = 0.f;

#pragma unroll
            for (int ks = 0; ks < 8; ++ks) {
                const uint32_t kb = kvb + (ks >> 2) * KTB + (ks & 3) * 32 + bOff;
                uint32_t bfr[4][4];
#pragma unroll
                for (int jp = 0; jp < 4; ++jp)
                    ldm4(bfr[jp][0], bfr[jp][1], bfr[jp][2], bfr[jp][3],
                         kb + (uint32_t)(jp * 16 * 144));
#pragma unroll
                for (int jn = 0; jn < 8; ++jn)
                    mma_tf32(s[jn], aq[ks], bfr[jn >> 1][(jn & 1) * 2],
                             bfr[jn >> 1][(jn & 1) * 2 + 1]);
            }

            // ---- mask ----
            const bool need_mask = (s0 + 63 > warpRowMin) || (s0 + 63 >= TT);
            if (need_mask) {
#pragma unroll
                for (int jn = 0; jn < 8; ++jn) {
                    int sc = s0 + 8 * jn + 2 * tq;
#pragma unroll
                    for (int c = 0; c < 4; ++c) {
                        int sidx = sc + (c & 1);
                        int t = (c < 2) ? rowA : rowB;
                        bool ok = (sidx < TT) && (sidx <= t || t == 0);
                        if (!ok) s[jn][c] = -1e30f;
                    }
                }
            }

            // ---- online softmax (log2 domain) ----
            float tmA = -1e30f, tmB = -1e30f;
#pragma unroll
            for (int jn = 0; jn < 8; ++jn) {
                tmA = fmaxf(tmA, fmaxf(s[jn][0], s[jn][1]));
                tmB = fmaxf(tmB, fmaxf(s[jn][2], s[jn][3]));
            }
            tmA = fmaxf(tmA, __shfl_xor_sync(0xffffffffu, tmA, 1));
            tmA = fmaxf(tmA, __shfl_xor_sync(0xffffffffu, tmA, 2));
            tmB = fmaxf(tmB, __shfl_xor_sync(0xffffffffu, tmB, 1));
            tmB = fmaxf(tmB, __shfl_xor_sync(0xffffffffu, tmB, 2));

            float mAn = fmaxf(mA, tmA), mBn = fmaxf(mB, tmB);
            float facA = ex2f(mA - mAn), facB = ex2f(mB - mBn);
            mA = mAn; mB = mBn;

            float sumA = 0.f, sumB = 0.f;
#pragma unroll
            for (int jn = 0; jn < 8; ++jn) {
                s[jn][0] = ex2f(s[jn][0] - mAn);
                s[jn][1] = ex2f(s[jn][1] - mAn);
                s[jn][2] = ex2f(s[jn][2] - mBn);
                s[jn][3] = ex2f(s[jn][3] - mBn);
                sumA += s[jn][0] + s[jn][1];
                sumB += s[jn][2] + s[jn][3];
            }
            sumA += __shfl_xor_sync(0xffffffffu, sumA, 1);
            sumA += __shfl_xor_sync(0xffffffffu, sumA, 2);
            sumB += __shfl_xor_sync(0xffffffffu, sumB, 1);
            sumB += __shfl_xor_sync(0xffffffffu, sumB, 2);

            lA = lA * facA + sumA;
            lB = lB * facB + sumB;
#pragma unroll
            for (int d = 0; d < 8; ++d) {
                o[d][0] *= facA; o[d][1] *= facA;
                o[d][2] *= facB; o[d][3] *= facB;
            }

            // ---- pack P to bf16 hi/lo ----
            uint32_t ph[4][4], pl[4][4];
#pragma unroll
            for (int k = 0; k < 4; ++k) {
                pack_hilo(s[2*k][0],   s[2*k][1],   ph[k][0], pl[k][0]);
                pack_hilo(s[2*k][2],   s[2*k][3],   ph[k][1], pl[k][1]);
                pack_hilo(s[2*k+1][0], s[2*k+1][1], ph[k][2], pl[k][2]);
                pack_hilo(s[2*k+1][2], s[2*k+1][3], ph[k][3], pl[k][3]);
            }

            // ---- O += P V (bf16x3) ----
#pragma unroll
            for (int k = 0; k < 4; ++k) {
                const uint32_t vbase = kvb + 2 * KTB + (uint32_t)(16 * k * 144) + vrowpart;
#pragma unroll
                for (int jd = 0; jd < 4; ++jd) {
                    uint32_t vh0, vh1, vh2, vh3, vl0, vl1, vl2, vl3;
                    ldm4t(vh0, vh1, vh2, vh3, vbase + jd * 32);
                    ldm4t(vl0, vl1, vl2, vl3, vbase + jd * 32 + KTB);
                    mma_bf16(o[2*jd],   ph[k], vh0, vh1);
                    mma_bf16(o[2*jd],   ph[k], vl0, vl1);
                    mma_bf16(o[2*jd],   pl[k], vh0, vh1);
                    mma_bf16(o[2*jd+1], ph[k], vh2, vh3);
                    mma_bf16(o[2*jd+1], ph[k], vl2, vl3);
                    mma_bf16(o[2*jd+1], pl[k], vh2, vh3);
                }
            }
        }

        cp_wait1();
        __syncthreads();
        slot = (slot == 2) ? 0 : slot + 1;
    }

    // epilogue — write y tf32-rounded (proj GEMM reads it raw)
    if (rowA < TT) {
        float il = 1.f / lA;
        float* dst = y + (size_t)(b * TT + rowA) * CC + h * 64 + tq * 2;
#pragma unroll
        for (int d = 0; d < 8; ++d)
            *(float2*)(dst + d * 8) =
                make_float2(rnd_tf32(o[d][0] * il), rnd_tf32(o[d][1] * il));
    }
    if (rowB < TT) {
        float il = 1.f / lB;
        float* dst = y + (size_t)(b * TT + rowB) * CC + h * 64 + tq * 2;
#pragma unroll
        for (int d = 0; d < 8; ++d)
            *(float2*)(dst + d * 8) =
                make_float2(rnd_tf32(o[d][2] * il), rnd_tf32(o[d][3] * il));
    }
}

// ---------------------------------------------------------------------------
extern "C" void kernel_launch(void* const* d_in, const int* in_sizes, int n_in,
                              void* d_out, int out_size)
{
    const float* x      = (const float*)d_in[0];
    const float* W_attn = (const float*)d_in[1];
    const float* W_proj = (const float*)d_in[2];
    float* out = (float*)d_out;

    float *xr = nullptr, *y = nullptr, *wt_attn = nullptr, *wt_proj = nullptr;
    float *qf = nullptr, *kf = nullptr;
    __nv_bfloat16 *vh = nullptr, *vl = nullptr;
    cudaGetSymbolAddress((void**)&xr, g_xr);
    cudaGetSymbolAddress((void**)&y, g_y);
    cudaGetSymbolAddress((void**)&wt_attn, g_wt_attn);
    cudaGetSymbolAddress((void**)&wt_proj, g_wt_proj);
    cudaGetSymbolAddress((void**)&qf, g_qf);
    cudaGetSymbolAddress((void**)&kf, g_kf);
    cudaGetSymbolAddress((void**)&vh, g_vh);
    cudaGetSymbolAddress((void**)&vl, g_vl);

    cudaFuncSetAttribute(tc_gemm2_kernel<0>,
                         cudaFuncAttributeMaxDynamicSharedMemorySize, GSMEM);
    cudaFuncSetAttribute(tc_gemm2_kernel<1>,
                         cudaFuncAttributeMaxDynamicSharedMemorySize, GSMEM);
    cudaFuncSetAttribute(attn_tc_kernel,
                         cudaFuncAttributeMaxDynamicSharedMemorySize, ATT_SMEM);

    // 0) round x; transpose+round weights
    {
        size_t n4 = (size_t)MROWS * CC / 4;
        round_kernel<<<(int)((n4 + 255) / 256), 256>>>(x, xr, n4);
        dim3 blk(32, 8);
        transpose_kernel<<<dim3(QKV_COLS / 32, CC / 32), blk>>>(W_attn, wt_attn, CC, QKV_COLS);
        transpose_kernel<<<dim3(CC / 32, CC / 32), blk>>>(W_proj, wt_proj, CC, CC);
    }

    // 1) qkv GEMM: epilogue writes Q (fp32*QSCALE), K (fp32), V (bf16 hi/lo)
    {
        dim3 grid(QKV_COLS / 128, (MROWS + 127) / 128);
        tc_gemm2_kernel<1><<<grid, 256, GSMEM>>>(
            xr, wt_attn, nullptr, qf, kf, vh, vl, MROWS, QKV_COLS, CC);
    }

    // 2) attention -> y
    {
        dim3 grid(17, BB * HH);
        attn_tc_kernel<<<grid, 256, ATT_SMEM>>>(qf, kf, vh, vl, y);
    }

    // 3) out = y @ W_proj
    {
        dim3 grid(CC / 128, (MROWS + 127) / 128);
        tc_gemm2_kernel<0><<<grid, 256, GSMEM>>>(
            y, wt_proj, out, nullptr, nullptr, nullptr, nullptr, MROWS, CC, CC);
    }
}

// round 9
// speedup vs baseline: 3.9406x; 1.0902x over previous
#include <cuda_runtime.h>
#include <cuda_bf16.h>
#include <math.h>
#include <stdint.h>

// Problem constants
#define BB 4
#define TT 2049
#define CC 1024
#define HH 16
#define DD 64
#define MROWS (BB*TT)          // 8196
#define QKV_COLS (3*CC)        // 3072

// Scratch (device globals: allocation-free, graph-capturable)
__device__ float g_xr[(size_t)MROWS * CC];          // x, tf32-rounded
__device__ float g_y[(size_t)MROWS * CC];           // attention out (tf32-rounded)
__device__ float g_wt_attn[(size_t)QKV_COLS * CC];  // W_attn^T (tf32-rounded)
__device__ float g_wt_proj[(size_t)CC * CC];        // W_proj^T (tf32-rounded)
__device__ float g_qf[(size_t)MROWS * CC];          // Q (tf32-rounded, * log2e/8)
__device__ float g_kf[(size_t)MROWS * CC];          // K (tf32-rounded)
__device__ __nv_bfloat16 g_vh[(size_t)MROWS * CC];  // V hi
__device__ __nv_bfloat16 g_vl[(size_t)MROWS * CC];  // V lo

#define QSCALE 0.18033688011112042f   // 0.125 * log2(e)

// ---------------------------------------------------------------------------
// helpers
// ---------------------------------------------------------------------------
__device__ __forceinline__ uint32_t smem_u32(const void* p) {
    uint32_t a;
    asm("{ .reg .u64 t; cvta.to.shared.u64 t, %1; cvt.u32.u64 %0, t; }" : "=r"(a) : "l"(p));
    return a;
}
__device__ __forceinline__ void cp16(uint32_t s, const void* g) {
    asm volatile("cp.async.cg.shared.global [%0], [%1], 16;" :: "r"(s), "l"(g));
}
__device__ __forceinline__ void cp_commit() {
    asm volatile("cp.async.commit_group;" ::: "memory");
}
__device__ __forceinline__ void cp_wait1() {
    asm volatile("cp.async.wait_group 1;" ::: "memory");
}
__device__ __forceinline__ uint32_t f2tf32(float f) {
    uint32_t u;
    asm("cvt.rna.tf32.f32 %0, %1;" : "=r"(u) : "f"(f));
    return u;
}
__device__ __forceinline__ float rnd_tf32(float f) {
    return __uint_as_float(f2tf32(f));
}
__device__ __forceinline__ float ex2f(float f) {
    float r;
    asm("ex2.approx.f32 %0, %1;" : "=f"(r) : "f"(f));
    return r;
}
__device__ __forceinline__ void mma_tf32(float* d, const uint32_t* a, uint32_t b0, uint32_t b1) {
    asm volatile(
        "mma.sync.aligned.m16n8k8.row.col.f32.tf32.tf32.f32 "
        "{%0,%1,%2,%3}, {%4,%5,%6,%7}, {%8,%9}, {%0,%1,%2,%3};"
        : "+f"(d[0]), "+f"(d[1]), "+f"(d[2]), "+f"(d[3])
        : "r"(a[0]), "r"(a[1]), "r"(a[2]), "r"(a[3]), "r"(b0), "r"(b1));
}
__device__ __forceinline__ void mma_bf16(float* d, const uint32_t* a, uint32_t b0, uint32_t b1) {
    asm volatile(
        "mma.sync.aligned.m16n8k16.row.col.f32.bf16.bf16.f32 "
        "{%0,%1,%2,%3}, {%4,%5,%6,%7}, {%8,%9}, {%0,%1,%2,%3};"
        : "+f"(d[0]), "+f"(d[1]), "+f"(d[2]), "+f"(d[3])
        : "r"(a[0]), "r"(a[1]), "r"(a[2]), "r"(a[3]), "r"(b0), "r"(b1));
}
__device__ __forceinline__ void ldm4(uint32_t& r0, uint32_t& r1, uint32_t& r2, uint32_t& r3,
                                     uint32_t a) {
    asm volatile("ldmatrix.sync.aligned.m8n8.x4.shared.b16 {%0,%1,%2,%3}, [%4];"
                 : "=r"(r0), "=r"(r1), "=r"(r2), "=r"(r3) : "r"(a));
}
__device__ __forceinline__ void ldm4t(uint32_t& r0, uint32_t& r1, uint32_t& r2, uint32_t& r3,
                                      uint32_t a) {
    asm volatile("ldmatrix.sync.aligned.m8n8.x4.trans.shared.b16 {%0,%1,%2,%3}, [%4];"
                 : "=r"(r0), "=r"(r1), "=r"(r2), "=r"(r3) : "r"(a));
}
// split two fp32 into packed bf16 hi + lo (low half = p0)
__device__ __forceinline__ void pack_hilo(float p0, float p1, uint32_t& hi, uint32_t& lo) {
    uint32_t hh;
    asm("cvt.rn.bf16x2.f32 %0, %1, %2;" : "=r"(hh) : "f"(p1), "f"(p0));
    float h0 = __uint_as_float(hh << 16);
    float h1 = __uint_as_float(hh & 0xffff0000u);
    float l0 = p0 - h0, l1 = p1 - h1;
    uint32_t ll;
    asm("cvt.rn.bf16x2.f32 %0, %1, %2;" : "=r"(ll) : "f"(l1), "f"(l0));
    hi = hh; lo = ll;
}

// ---------------------------------------------------------------------------
// Transpose + tf32 round: out[c][r] = rnd(in[r][c])
// ---------------------------------------------------------------------------
__global__ __launch_bounds__(256) void transpose_kernel(
    const float* __restrict__ in, float* __restrict__ out, int R, int Ccols)
{
    __shared__ float t[32][33];
    int x = blockIdx.x * 32 + threadIdx.x;
    int y0 = blockIdx.y * 32;
#pragma unroll
    for (int j = threadIdx.y; j < 32; j += 8)
        t[j][threadIdx.x] = in[(size_t)(y0 + j) * Ccols + x];
    __syncthreads();
    int ox = y0 + threadIdx.x;
    int oy0 = blockIdx.x * 32;
#pragma unroll
    for (int j = threadIdx.y; j < 32; j += 8)
        out[(size_t)(oy0 + j) * R + ox] = rnd_tf32(t[threadIdx.x][j]);
}

// ---------------------------------------------------------------------------
// Elementwise tf32 round (float4)
// ---------------------------------------------------------------------------
__global__ __launch_bounds__(256) void round_kernel(
    const float* __restrict__ in, float* __restrict__ out, size_t n4)
{
    size_t i = (size_t)blockIdx.x * 256 + threadIdx.x;
    if (i < n4) {
        float4 v = ((const float4*)in)[i];
        v.x = rnd_tf32(v.x); v.y = rnd_tf32(v.y);
        v.z = rnd_tf32(v.z); v.w = rnd_tf32(v.w);
        ((float4*)out)[i] = v;
    }
}

// ---------------------------------------------------------------------------
// TF32 tensor-core GEMM, 3-stage single-sync pipeline (unchanged).
// ---------------------------------------------------------------------------
#define GTILEB 18432                 // 128 x 36 floats
#define GSTAGE (2 * GTILEB)          // A + B
#define GSMEM (3 * GSTAGE)           // 110592

template<int MODE>
__global__ __launch_bounds__(256, 2) void tc_gemm2_kernel(
    const float* __restrict__ A, const float* __restrict__ Bt,
    float* __restrict__ Cf, float* __restrict__ Qf, float* __restrict__ Kf,
    __nv_bfloat16* __restrict__ Vh, __nv_bfloat16* __restrict__ Vl,
    int M, int N, int K)
{
    extern __shared__ float gsm[];
    const uint32_t sb = smem_u32(gsm);
    const uint32_t aBase[3] = { sb, sb + GSTAGE, sb + 2 * GSTAGE };
    const uint32_t bBase[3] = { sb + GTILEB, sb + GSTAGE + GTILEB, sb + 2 * GSTAGE + GTILEB };

    const int tid  = threadIdx.x;
    const int warp = tid >> 5;
    const int lane = tid & 31;
    const int wm = warp >> 2;
    const int wn = warp & 3;
    const int g  = lane >> 2;
    const int tq = lane & 3;

    const int bm = blockIdx.y * 128;
    const int bn = blockIdx.x * 128;
    const int NT = K >> 5;

    auto load_stage = [&](int s, int k0) {
#pragma unroll
        for (int i = 0; i < 4; ++i) {
            int u = tid + (i << 8);
            int r = u >> 3, c = u & 7;
            int ar = bm + r; if (ar >= M) ar = M - 1;
            cp16(aBase[s] + (uint32_t)(r * 144 + c * 16),
                 A + (size_t)ar * K + k0 + c * 4);
        }
#pragma unroll
        for (int i = 0; i < 4; ++i) {
            int u = tid + (i << 8);
            int r = u >> 3, c = u & 7;
            int br = bn + r; if (br >= N) br = N - 1;
            cp16(bBase[s] + (uint32_t)(r * 144 + c * 16),
                 Bt + (size_t)br * K + k0 + c * 4);
        }
    };

    const int sub = lane >> 3, srow = lane & 7;
    const uint32_t aOff = (uint32_t)(((sub & 1) * 8 + srow) * 144 + (sub >> 1) * 16);
    const uint32_t bOff = (uint32_t)(((sub >> 1) * 8 + srow) * 144 + (sub & 1) * 16);

    float acc[4][4][4];
#pragma unroll
    for (int i = 0; i < 4; ++i)
#pragma unroll
        for (int j = 0; j < 4; ++j)
#pragma unroll
            for (int r = 0; r < 4; ++r) acc[i][j][r] = 0.f;

    load_stage(0, 0);
    cp_commit();
    load_stage(1, 32);
    cp_commit();
    cp_wait1();
    __syncthreads();

    int slot = 0;
    for (int kt = 0; kt < NT; ++kt) {
        const int nst = kt + 2;
        if (nst < NT) load_stage(nst % 3, nst << 5);
        cp_commit();

        const uint32_t aW = aBase[slot] + (uint32_t)(wm * 64 * 144) + aOff;
        const uint32_t bW = bBase[slot] + (uint32_t)(wn * 32 * 144) + bOff;

#pragma unroll
        for (int ks = 0; ks < 4; ++ks) {
            uint32_t af[4][4], bf[2][4];
#pragma unroll
            for (int im = 0; im < 4; ++im)
                ldm4(af[im][0], af[im][1], af[im][2], af[im][3],
                     aW + (uint32_t)(im * 16 * 144) + ks * 32);
#pragma unroll
            for (int jp = 0; jp < 2; ++jp)
                ldm4(bf[jp][0], bf[jp][1], bf[jp][2], bf[jp][3],
                     bW + (uint32_t)(jp * 16 * 144) + ks * 32);
#pragma unroll
            for (int im = 0; im < 4; ++im)
#pragma unroll
                for (int jn = 0; jn < 4; ++jn)
                    mma_tf32(acc[im][jn], af[im], bf[jn >> 1][(jn & 1) * 2],
                             bf[jn >> 1][(jn & 1) * 2 + 1]);
        }

        cp_wait1();
        __syncthreads();
        slot = (slot == 2) ? 0 : slot + 1;
    }

    // epilogue
#pragma unroll
    for (int im = 0; im < 4; ++im) {
        const int r0 = bm + wm * 64 + im * 16 + g;
#pragma unroll
        for (int jn = 0; jn < 4; ++jn) {
            const int cc = bn + wn * 32 + jn * 8 + tq * 2;
            if (MODE == 0) {
                if (r0 < M)
                    *(float2*)&Cf[(size_t)r0 * N + cc] =
                        make_float2(acc[im][jn][0], acc[im][jn][1]);
                if (r0 + 8 < M)
                    *(float2*)&Cf[(size_t)(r0 + 8) * N + cc] =
                        make_float2(acc[im][jn][2], acc[im][jn][3]);
            } else {
                if (cc < CC) {            // Q: fp32, * log2e/8, tf32-rounded
                    if (r0 < M)
                        *(float2*)&Qf[(size_t)r0 * CC + cc] =
                            make_float2(rnd_tf32(acc[im][jn][0] * QSCALE),
                                        rnd_tf32(acc[im][jn][1] * QSCALE));
                    if (r0 + 8 < M)
                        *(float2*)&Qf[(size_t)(r0 + 8) * CC + cc] =
                            make_float2(rnd_tf32(acc[im][jn][2] * QSCALE),
                                        rnd_tf32(acc[im][jn][3] * QSCALE));
                } else if (cc < 2 * CC) { // K: fp32, tf32-rounded
                    int kc = cc - CC;
                    if (r0 < M)
                        *(float2*)&Kf[(size_t)r0 * CC + kc] =
                            make_float2(rnd_tf32(acc[im][jn][0]),
                                        rnd_tf32(acc[im][jn][1]));
                    if (r0 + 8 < M)
                        *(float2*)&Kf[(size_t)(r0 + 8) * CC + kc] =
                            make_float2(rnd_tf32(acc[im][jn][2]),
                                        rnd_tf32(acc[im][jn][3]));
                } else {                  // V: bf16 hi/lo split
                    int vc = cc - 2 * CC;
                    if (r0 < M) {
                        uint32_t h, l;
                        pack_hilo(acc[im][jn][0], acc[im][jn][1], h, l);
                        size_t o = ((size_t)r0 * CC + vc) >> 1;
                        ((uint32_t*)Vh)[o] = h;
                        ((uint32_t*)Vl)[o] = l;
                    }
                    if (r0 + 8 < M) {
                        uint32_t h, l;
                        pack_hilo(acc[im][jn][2], acc[im][jn][3], h, l);
                        size_t o = ((size_t)(r0 + 8) * CC + vc) >> 1;
                        ((uint32_t*)Vh)[o] = h;
                        ((uint32_t*)Vl)[o] = l;
                    }
                }
            }
        }
    }
}

// ---------------------------------------------------------------------------
// Flash attention: 64 q-rows x (b,h) per CTA, 128 threads (4 warps, m16 each),
// 2 CTAs/SM. S = QK^T tf32, PV bf16x3, log2 softmax. 64-key tiles,
// 2-stage cp.async double buffer.
// smem: Q 2x9216 ; 2 stages x [K0 K1 Vh Vl] x 9216.
// ---------------------------------------------------------------------------
#define KTB 9216
#define QTB64 9216                   // 64 rows x 32 floats (144B pitch)
#define ASTAGE (4 * KTB)             // 36864
#define ATT_SMEM (2 * QTB64 + 2 * ASTAGE)   // 92160

__global__ __launch_bounds__(128, 2) void attn_tc_kernel(
    const float* __restrict__ qf, const float* __restrict__ kf,
    const __nv_bfloat16* __restrict__ vh_g, const __nv_bfloat16* __restrict__ vl_g,
    float* __restrict__ y)
{
    extern __shared__ char asmem[];
    const uint32_t sb = smem_u32(asmem);
    const uint32_t Qb = sb;
    const uint32_t KV = sb + 2 * QTB64;

    const int tid = threadIdx.x, warp = tid >> 5, lane = tid & 31;
    const int g = lane >> 2, tq = lane & 3;
    const int qt = blockIdx.x, bh = blockIdx.y;
    const int b = bh >> 4, h = bh & 15;
    const int t0 = qt * 64;
    const int nk = (qt == 0) ? 33 : (qt + 1);

    const float* qsrc = qf + (size_t)b * TT * CC + h * 64;
    const float* ksrc = kf + (size_t)b * TT * CC + h * 64;
    const __nv_bfloat16* vhsrc = vh_g + (size_t)b * TT * CC + h * 64;
    const __nv_bfloat16* vlsrc = vl_g + (size_t)b * TT * CC + h * 64;

    auto load_q = [&]() {
#pragma unroll
        for (int st = 0; st < 2; ++st)
#pragma unroll
            for (int i = 0; i < 4; ++i) {
                int u = tid + (i << 7);
                int r = u >> 3, c = u & 7;
                int t = t0 + r; if (t >= TT) t = TT - 1;
                cp16(Qb + st * QTB64 + r * 144 + c * 16,
                     qsrc + (size_t)t * CC + st * 32 + c * 4);
            }
    };

    auto load_kv = [&](int slot, int s0) {
        uint32_t base = KV + slot * ASTAGE;
#pragma unroll
        for (int st = 0; st < 2; ++st)
#pragma unroll
            for (int i = 0; i < 4; ++i) {
                int u = tid + (i << 7);
                int r = u >> 3, c = u & 7;
                int s = s0 + r; if (s >= TT) s = TT - 1;
                cp16(base + st * KTB + r * 144 + c * 16,
                     ksrc + (size_t)s * CC + st * 32 + c * 4);
            }
#pragma unroll
        for (int i = 0; i < 4; ++i) {
            int u = tid + (i << 7);
            int r = u >> 3, c = u & 7;
            int s = s0 + r; if (s >= TT) s = TT - 1;
            cp16(base + 2 * KTB + r * 144 + c * 16, vhsrc + (size_t)s * CC + c * 8);
        }
#pragma unroll
        for (int i = 0; i < 4; ++i) {
            int u = tid + (i << 7);
            int r = u >> 3, c = u & 7;
            int s = s0 + r; if (s >= TT) s = TT - 1;
            cp16(base + 3 * KTB + r * 144 + c * 16, vlsrc + (size_t)s * CC + c * 8);
        }
    };

    // prologue: (Q + stage0) | stage1
    load_q();
    load_kv(0, 0);
    cp_commit();
    load_kv(1, 64);
    cp_commit();
    cp_wait1();        // Q + stage0 resident
    __syncthreads();

    const int sub = lane >> 3, srow = lane & 7;
    const uint32_t aOff = (uint32_t)(((sub & 1) * 8 + srow) * 144 + (sub >> 1) * 16);
    const uint32_t bOff = (uint32_t)(((sub >> 1) * 8 + srow) * 144 + (sub & 1) * 16);
    const uint32_t vrowpart = (uint32_t)(((lane & 7) + ((lane >> 3) & 1) * 8) * 144
                                         + ((lane >> 4) & 1) * 16);

    uint32_t aq[8][4];
#pragma unroll
    for (int ks = 0; ks < 8; ++ks)
        ldm4(aq[ks][0], aq[ks][1], aq[ks][2], aq[ks][3],
             Qb + (ks >> 2) * QTB64 + (uint32_t)(warp * 16 * 144) + aOff + (ks & 3) * 32);

    const int rowA = t0 + warp * 16 + g;
    const int rowB = rowA + 8;
    const int warpRowMin = t0 + warp * 16;
    const int warpRowMax = warpRowMin + 15;
    const bool hasRow0 = (warpRowMin == 0);

    float mA = -INFINITY, mB = -INFINITY, lA = 0.f, lB = 0.f;
    float o[8][4];
#pragma unroll
    for (int d = 0; d < 8; ++d)
#pragma unroll
        for (int c = 0; c < 4; ++c) o[d][c] = 0.f;

    for (int kt = 0; kt < nk; ++kt) {
        const int s0 = kt * 64;
        const int slot = kt & 1;
        const uint32_t kvb = KV + slot * ASTAGE;
        const bool active = (s0 <= warpRowMax) || hasRow0;

        if (active) {
            // ---- S = Q K^T (tf32) ----
            float s[8][4];
#pragma unroll
            for (int j = 0; j < 8; ++j)
#pragma unroll
                for (int c = 0; c < 4; ++c) s[j][c] = 0.f;

#pragma unroll
            for (int ks = 0; ks < 8; ++ks) {
                const uint32_t kb = kvb + (ks >> 2) * KTB + (ks & 3) * 32 + bOff;
                uint32_t bfr[4][4];
#pragma unroll
                for (int jp = 0; jp < 4; ++jp)
                    ldm4(bfr[jp][0], bfr[jp][1], bfr[jp][2], bfr[jp][3],
                         kb + (uint32_t)(jp * 16 * 144));
#pragma unroll
                for (int jn = 0; jn < 8; ++jn)
                    mma_tf32(s[jn], aq[ks], bfr[jn >> 1][(jn & 1) * 2],
                             bfr[jn >> 1][(jn & 1) * 2 + 1]);
            }

            // ---- mask ----
            const bool need_mask = (s0 + 63 > warpRowMin) || (s0 + 63 >= TT);
            if (need_mask) {
#pragma unroll
                for (int jn = 0; jn < 8; ++jn) {
                    int sc = s0 + 8 * jn + 2 * tq;
#pragma unroll
                    for (int c = 0; c < 4; ++c) {
                        int sidx = sc + (c & 1);
                        int t = (c < 2) ? rowA : rowB;
                        bool ok = (sidx < TT) && (sidx <= t || t == 0);
                        if (!ok) s[jn][c] = -1e30f;
                    }
                }
            }

            // ---- online softmax (log2 domain) ----
            float tmA = -1e30f, tmB = -1e30f;
#pragma unroll
            for (int jn = 0; jn < 8; ++jn) {
                tmA = fmaxf(tmA, fmaxf(s[jn][0], s[jn][1]));
                tmB = fmaxf(tmB, fmaxf(s[jn][2], s[jn][3]));
            }
            tmA = fmaxf(tmA, __shfl_xor_sync(0xffffffffu, tmA, 1));
            tmA = fmaxf(tmA, __shfl_xor_sync(0xffffffffu, tmA, 2));
            tmB = fmaxf(tmB, __shfl_xor_sync(0xffffffffu, tmB, 1));
            tmB = fmaxf(tmB, __shfl_xor_sync(0xffffffffu, tmB, 2));

            float mAn = fmaxf(mA, tmA), mBn = fmaxf(mB, tmB);
            float facA = ex2f(mA - mAn), facB = ex2f(mB - mBn);
            mA = mAn; mB = mBn;

            float sumA = 0.f, sumB = 0.f;
#pragma unroll
            for (int jn = 0; jn < 8; ++jn) {
                s[jn][0] = ex2f(s[jn][0] - mAn);
                s[jn][1] = ex2f(s[jn][1] - mAn);
                s[jn][2] = ex2f(s[jn][2] - mBn);
                s[jn][3] = ex2f(s[jn][3] - mBn);
                sumA += s[jn][0] + s[jn][1];
                sumB += s[jn][2] + s[jn][3];
            }
            sumA += __shfl_xor_sync(0xffffffffu, sumA, 1);
            sumA += __shfl_xor_sync(0xffffffffu, sumA, 2);
            sumB += __shfl_xor_sync(0xffffffffu, sumB, 1);
            sumB += __shfl_xor_sync(0xffffffffu, sumB, 2);

            lA = lA * facA + sumA;
            lB = lB * facB + sumB;
#pragma unroll
            for (int d = 0; d < 8; ++d) {
                o[d][0] *= facA; o[d][1] *= facA;
                o[d][2] *= facB; o[d][3] *= facB;
            }

            // ---- pack P to bf16 hi/lo ----
            uint32_t ph[4][4], pl[4][4];
#pragma unroll
            for (int k = 0; k < 4; ++k) {
                pack_hilo(s[2*k][0],   s[2*k][1],   ph[k][0], pl[k][0]);
                pack_hilo(s[2*k][2],   s[2*k][3],   ph[k][1], pl[k][1]);
                pack_hilo(s[2*k+1][0], s[2*k+1][1], ph[k][2], pl[k][2]);
                pack_hilo(s[2*k+1][2], s[2*k+1][3], ph[k][3], pl[k][3]);
            }

            // ---- O += P V (bf16x3) ----
#pragma unroll
            for (int k = 0; k < 4; ++k) {
                const uint32_t vbase = kvb + 2 * KTB + (uint32_t)(16 * k * 144) + vrowpart;
#pragma unroll
                for (int jd = 0; jd < 4; ++jd) {
                    uint32_t vh0, vh1, vh2, vh3, vl0, vl1, vl2, vl3;
                    ldm4t(vh0, vh1, vh2, vh3, vbase + jd * 32);
                    ldm4t(vl0, vl1, vl2, vl3, vbase + jd * 32 + KTB);
                    mma_bf16(o[2*jd],   ph[k], vh0, vh1);
                    mma_bf16(o[2*jd],   ph[k], vl0, vl1);
                    mma_bf16(o[2*jd],   pl[k], vh0, vh1);
                    mma_bf16(o[2*jd+1], ph[k], vh2, vh3);
                    mma_bf16(o[2*jd+1], ph[k], vl2, vl3);
                    mma_bf16(o[2*jd+1], pl[k], vh2, vh3);
                }
            }
        }

        // done reading slot; refill it with stage kt+2, then wait for kt+1
        __syncthreads();
        if (kt + 2 < nk) load_kv(slot, (kt + 2) * 64);
        cp_commit();
        cp_wait1();
        __syncthreads();
    }

    // epilogue — write y tf32-rounded (proj GEMM reads it raw)
    if (rowA < TT) {
        float il = 1.f / lA;
        float* dst = y + (size_t)(b * TT + rowA) * CC + h * 64 + tq * 2;
#pragma unroll
        for (int d = 0; d < 8; ++d)
            *(float2*)(dst + d * 8) =
                make_float2(rnd_tf32(o[d][0] * il), rnd_tf32(o[d][1] * il));
    }
    if (rowB < TT) {
        float il = 1.f / lB;
        float* dst = y + (size_t)(b * TT + rowB) * CC + h * 64 + tq * 2;
#pragma unroll
        for (int d = 0; d < 8; ++d)
            *(float2*)(dst + d * 8) =
                make_float2(rnd_tf32(o[d][2] * il), rnd_tf32(o[d][3] * il));
    }
}

// ---------------------------------------------------------------------------
extern "C" void kernel_launch(void* const* d_in, const int* in_sizes, int n_in,
                              void* d_out, int out_size)
{
    const float* x      = (const float*)d_in[0];
    const float* W_attn = (const float*)d_in[1];
    const float* W_proj = (const float*)d_in[2];
    float* out = (float*)d_out;

    float *xr = nullptr, *y = nullptr, *wt_attn = nullptr, *wt_proj = nullptr;
    float *qf = nullptr, *kf = nullptr;
    __nv_bfloat16 *vh = nullptr, *vl = nullptr;
    cudaGetSymbolAddress((void**)&xr, g_xr);
    cudaGetSymbolAddress((void**)&y, g_y);
    cudaGetSymbolAddress((void**)&wt_attn, g_wt_attn);
    cudaGetSymbolAddress((void**)&wt_proj, g_wt_proj);
    cudaGetSymbolAddress((void**)&qf, g_qf);
    cudaGetSymbolAddress((void**)&kf, g_kf);
    cudaGetSymbolAddress((void**)&vh, g_vh);
    cudaGetSymbolAddress((void**)&vl, g_vl);

    cudaFuncSetAttribute(tc_gemm2_kernel<0>,
                         cudaFuncAttributeMaxDynamicSharedMemorySize, GSMEM);
    cudaFuncSetAttribute(tc_gemm2_kernel<1>,
                         cudaFuncAttributeMaxDynamicSharedMemorySize, GSMEM);
    cudaFuncSetAttribute(attn_tc_kernel,
                         cudaFuncAttributeMaxDynamicSharedMemorySize, ATT_SMEM);

    // 0) round x; transpose+round weights
    {
        size_t n4 = (size_t)MROWS * CC / 4;
        round_kernel<<<(int)((n4 + 255) / 256), 256>>>(x, xr, n4);
        dim3 blk(32, 8);
        transpose_kernel<<<dim3(QKV_COLS / 32, CC / 32), blk>>>(W_attn, wt_attn, CC, QKV_COLS);
        transpose_kernel<<<dim3(CC / 32, CC / 32), blk>>>(W_proj, wt_proj, CC, CC);
    }

    // 1) qkv GEMM: epilogue writes Q (fp32*QSCALE), K (fp32), V (bf16 hi/lo)
    {
        dim3 grid(QKV_COLS / 128, (MROWS + 127) / 128);
        tc_gemm2_kernel<1><<<grid, 256, GSMEM>>>(
            xr, wt_attn, nullptr, qf, kf, vh, vl, MROWS, QKV_COLS, CC);
    }

    // 2) attention -> y  (64-row CTAs, 2/SM)
    {
        dim3 grid(33, BB * HH);
        attn_tc_kernel<<<grid, 128, ATT_SMEM>>>(qf, kf, vh, vl, y);
    }

    // 3) out = y @ W_proj
    {
        dim3 grid(CC / 128, (MROWS + 127) / 128);
        tc_gemm2_kernel<0><<<grid, 256, GSMEM>>>(
            y, wt_proj, out, nullptr, nullptr, nullptr, nullptr, MROWS, CC, CC);
    }
}